// round 2
// baseline (speedup 1.0000x reference)
#include <cuda_runtime.h>
#include <cuda_bf16.h>
#include <math.h>

// ---------------- problem constants ----------------
#define G        160
#define V        (G*G*G)          // 4,096,000 voxels
#define NRAYS    4096
#define S        256
#define NS       (NRAYS*S)        // 1,048,576 samples
#define C0CH     12               // k0 channels
#define DIM0     39               // 12 + 3 + 12 + 12
#define W        128
#define TILE     128              // samples per MLP block
#define ACT_SHIFT (-4.5951198501345898f)   // log(0.01/0.99)

// ---------------- scratch (device globals; no allocation allowed) ----------
__device__ float g_inter[(size_t)V * 16];   // [vox][16]: ch0..11 = k0, ch12 = density, 13..15 = 0
__device__ float g_sp[NS];                  // softplus(dens + shift)
__device__ float g_rgb[(size_t)NS * 3];     // per-sample rgb (post-sigmoid)

// ---------------- f32x2 helpers ----------------
__device__ __forceinline__ unsigned long long pack2(float x, float y) {
    unsigned long long r;
    asm("mov.b64 %0, {%1, %2};" : "=l"(r) : "f"(x), "f"(y));
    return r;
}
__device__ __forceinline__ void unpack2(unsigned long long v, float& lo, float& hi) {
    asm("mov.b64 {%0, %1}, %2;" : "=f"(lo), "=f"(hi) : "l"(v));
}
__device__ __forceinline__ void fma2(unsigned long long& d, unsigned long long a, unsigned long long b) {
    asm("fma.rn.f32x2 %0, %1, %2, %0;" : "+l"(d) : "l"(a), "l"(b));
}

// ---------------- kernel 1: transpose grids to interleaved layout ----------
// 32 voxels per block, 512 threads. Coalesced reads per-channel, coalesced
// interleaved writes via smem staging.
__global__ void k_transpose(const float* __restrict__ dens,
                            const float* __restrict__ k0) {
    __shared__ float s[13][33];
    int v0 = blockIdx.x * 32;
    int t = threadIdx.x;
    if (t < 13 * 32) {
        int c = t >> 5, v = t & 31;
        float val = (c < 12) ? k0[(size_t)c * V + v0 + v] : dens[v0 + v];
        s[c][v] = val;
    }
    __syncthreads();
    {   // 512 = 32 voxels * 16 channels, fully coalesced write
        int v = t >> 4, c = t & 15;
        g_inter[(size_t)(v0 + v) * 16 + c] = (c < 13) ? s[c][v] : 0.0f;
    }
}

// ---------------- kernel 2: featurize + MLP ----------------
// One block = 128 samples, 256 threads.
// smem layout (floats):
#define OFF_W1   0
#define OFF_H1   (OFF_W1 + 128*128)          // 16384
#define OFF_FEAT (OFF_H1 + 128*129)          // +16512
#define OFF_W0   (OFF_FEAT + 128*41)         // +5248
#define OFF_B0   (OFF_W0 + 39*128)           // +4992
#define OFF_B1   (OFF_B0 + 128)
#define OFF_W2   (OFF_B1 + 128)
#define OFF_B2   (OFF_W2 + 128*3)
#define OFF_RGBA (OFF_B2 + 4)
#define SMEM_FLOATS (OFF_RGBA + 128*3)
#define SMEM_BYTES (SMEM_FLOATS * 4)

__global__ __launch_bounds__(256, 1)
void k_mlp(const float* __restrict__ pts,
           const float* __restrict__ viewdirs,
           const float* __restrict__ w0g, const float* __restrict__ b0g,
           const float* __restrict__ w1g, const float* __restrict__ b1g,
           const float* __restrict__ w2g, const float* __restrict__ b2g) {
    extern __shared__ float sm[];
    float* w1s   = sm + OFF_W1;
    float* h1s   = sm + OFF_H1;
    float* feats = sm + OFF_FEAT;
    float* w0s   = sm + OFF_W0;
    float* b0s   = sm + OFF_B0;
    float* b1s   = sm + OFF_B1;
    float* w2s   = sm + OFF_W2;
    float* rgba  = sm + OFF_RGBA;

    const int t = threadIdx.x;
    const int blk = blockIdx.x;

    // ---- load weights into smem ----
    for (int i = t; i < 39 * 128; i += 256) w0s[i] = w0g[i];
    for (int i = t; i < 128 * 128; i += 256) w1s[i] = w1g[i];
    for (int i = t; i < 128 * 3; i += 256) w2s[i] = w2g[i];
    if (t < 128) { b0s[t] = b0g[t]; b1s[t] = b1g[t]; }
    // rgb accumulator init = b2
    for (int i = t; i < 128 * 3; i += 256) rgba[i] = b2g[i % 3];

    // ---- per-sample featurize (threads 0..127) ----
    if (t < 128) {
        int gs = blk * TILE + t;           // global sample
        int ray = gs >> 8;

        const float* pp = pts + (size_t)gs * 3;
        float f[3]; int i0[3];
        #pragma unroll
        for (int d = 0; d < 3; d++) {
            float u = (pp[d] + 1.0f) * (0.5f * (G - 1));
            u = fminf(fmaxf(u, 0.0f), (float)(G - 1));
            int ii = (int)floorf(u);
            ii = min(ii, G - 2);
            f[d] = u - (float)ii;
            i0[d] = ii;
        }
        float wx[2] = {1.0f - f[0], f[0]};
        float wy[2] = {1.0f - f[1], f[1]};
        float wz[2] = {1.0f - f[2], f[2]};

        float acc[13];
        #pragma unroll
        for (int c = 0; c < 13; c++) acc[c] = 0.0f;

        #pragma unroll
        for (int dx = 0; dx < 2; dx++)
        #pragma unroll
        for (int dy = 0; dy < 2; dy++)
        #pragma unroll
        for (int dz = 0; dz < 2; dz++) {
            float wgt = wx[dx] * wy[dy] * wz[dz];
            int vox = ((i0[0] + dx) * G + (i0[1] + dy)) * G + (i0[2] + dz);
            const float4* cp = reinterpret_cast<const float4*>(g_inter) + (size_t)vox * 4;
            float4 A = cp[0], B = cp[1], Cc = cp[2], D = cp[3];
            acc[0]  += wgt * A.x;  acc[1]  += wgt * A.y;
            acc[2]  += wgt * A.z;  acc[3]  += wgt * A.w;
            acc[4]  += wgt * B.x;  acc[5]  += wgt * B.y;
            acc[6]  += wgt * B.z;  acc[7]  += wgt * B.w;
            acc[8]  += wgt * Cc.x; acc[9]  += wgt * Cc.y;
            acc[10] += wgt * Cc.z; acc[11] += wgt * Cc.w;
            acc[12] += wgt * D.x;
        }

        // density -> softplus, stored for compositing
        float dd = acc[12] + ACT_SHIFT;
        float spv = (dd > 15.0f) ? dd : log1pf(expf(dd));
        g_sp[gs] = spv;

        // view embedding
        float vx = viewdirs[ray * 3 + 0];
        float vy = viewdirs[ray * 3 + 1];
        float vz = viewdirs[ray * 3 + 2];
        float inv = rsqrtf(vx * vx + vy * vy + vz * vz);
        vx *= inv; vy *= inv; vz *= inv;

        float* fr = feats + t * 41;
        #pragma unroll
        for (int c = 0; c < 12; c++) fr[c] = acc[c];
        fr[12] = vx; fr[13] = vy; fr[14] = vz;
        float vdn[3] = {vx, vy, vz};
        #pragma unroll
        for (int d = 0; d < 3; d++) {
            #pragma unroll
            for (int fq = 0; fq < 4; fq++) {
                float ang = vdn[d] * (float)(1 << fq);
                float sv, cv;
                sincosf(ang, &sv, &cv);
                fr[15 + d * 4 + fq] = sv;
                fr[27 + d * 4 + fq] = cv;
            }
        }
    }
    __syncthreads();

    // ---- thread tile mapping: 4 rows (rt+32i) x 16 cols (ct*16..) ----
    const int rt = t & 31;
    const int ct = t >> 5;
    const int c0 = ct * 16;

    unsigned long long accp[4][8];

    // ===== GEMM1: h1 = relu(feat @ w0 + b0), K=39 =====
    {
        const ulonglong2* bp = reinterpret_cast<const ulonglong2*>(b0s + c0);
        ulonglong2 q0 = bp[0], q1 = bp[1], q2 = bp[2], q3 = bp[3];
        #pragma unroll
        for (int i = 0; i < 4; i++) {
            accp[i][0] = q0.x; accp[i][1] = q0.y;
            accp[i][2] = q1.x; accp[i][3] = q1.y;
            accp[i][4] = q2.x; accp[i][5] = q2.y;
            accp[i][6] = q3.x; accp[i][7] = q3.y;
        }
        for (int k = 0; k < 39; k++) {
            unsigned long long ap[4];
            #pragma unroll
            for (int i = 0; i < 4; i++) {
                float a = feats[(rt + 32 * i) * 41 + k];
                ap[i] = pack2(a, a);
            }
            const ulonglong2* wp = reinterpret_cast<const ulonglong2*>(w0s + k * 128 + c0);
            ulonglong2 wa = wp[0], wb = wp[1], wc = wp[2], wd = wp[3];
            unsigned long long wv[8] = {wa.x, wa.y, wb.x, wb.y, wc.x, wc.y, wd.x, wd.y};
            #pragma unroll
            for (int i = 0; i < 4; i++)
                #pragma unroll
                for (int j = 0; j < 8; j++)
                    fma2(accp[i][j], ap[i], wv[j]);
        }
        #pragma unroll
        for (int i = 0; i < 4; i++) {
            int base = (rt + 32 * i) * 129 + c0;
            #pragma unroll
            for (int j = 0; j < 8; j++) {
                float lo, hi;
                unpack2(accp[i][j], lo, hi);
                h1s[base + 2 * j]     = fmaxf(lo, 0.0f);
                h1s[base + 2 * j + 1] = fmaxf(hi, 0.0f);
            }
        }
    }
    __syncthreads();

    // ===== GEMM2: h2 = relu(h1 @ w1 + b1), K=128; fused GEMM3 epilogue =====
    {
        const ulonglong2* bp = reinterpret_cast<const ulonglong2*>(b1s + c0);
        ulonglong2 q0 = bp[0], q1 = bp[1], q2 = bp[2], q3 = bp[3];
        #pragma unroll
        for (int i = 0; i < 4; i++) {
            accp[i][0] = q0.x; accp[i][1] = q0.y;
            accp[i][2] = q1.x; accp[i][3] = q1.y;
            accp[i][4] = q2.x; accp[i][5] = q2.y;
            accp[i][6] = q3.x; accp[i][7] = q3.y;
        }
        for (int k = 0; k < 128; k++) {
            unsigned long long ap[4];
            #pragma unroll
            for (int i = 0; i < 4; i++) {
                float a = h1s[(rt + 32 * i) * 129 + k];
                ap[i] = pack2(a, a);
            }
            const ulonglong2* wp = reinterpret_cast<const ulonglong2*>(w1s + k * 128 + c0);
            ulonglong2 wa = wp[0], wb = wp[1], wc = wp[2], wd = wp[3];
            unsigned long long wv[8] = {wa.x, wa.y, wb.x, wb.y, wc.x, wc.y, wd.x, wd.y};
            #pragma unroll
            for (int i = 0; i < 4; i++)
                #pragma unroll
                for (int j = 0; j < 8; j++)
                    fma2(accp[i][j], ap[i], wv[j]);
        }
        // epilogue: relu then partial h2 @ w2 into smem accumulator
        #pragma unroll
        for (int i = 0; i < 4; i++) {
            int r = rt + 32 * i;
            float p0 = 0.0f, p1 = 0.0f, p2 = 0.0f;
            #pragma unroll
            for (int j = 0; j < 8; j++) {
                float lo, hi;
                unpack2(accp[i][j], lo, hi);
                lo = fmaxf(lo, 0.0f);
                hi = fmaxf(hi, 0.0f);
                int col = c0 + 2 * j;
                p0 += lo * w2s[col * 3 + 0] + hi * w2s[(col + 1) * 3 + 0];
                p1 += lo * w2s[col * 3 + 1] + hi * w2s[(col + 1) * 3 + 1];
                p2 += lo * w2s[col * 3 + 2] + hi * w2s[(col + 1) * 3 + 2];
            }
            atomicAdd(&rgba[r * 3 + 0], p0);
            atomicAdd(&rgba[r * 3 + 1], p1);
            atomicAdd(&rgba[r * 3 + 2], p2);
        }
    }
    __syncthreads();

    // ---- sigmoid + store per-sample rgb ----
    if (t < 128) {
        int gs = blk * TILE + t;
        #pragma unroll
        for (int c = 0; c < 3; c++) {
            float x = rgba[t * 3 + c];
            g_rgb[(size_t)gs * 3 + c] = 1.0f / (1.0f + expf(-x));
        }
    }
}

// ---------------- kernel 3: per-ray composite ----------------
// T = cumprod(1-alpha) = exp(-0.5 * cumsum(softplus)); scan + reduce per ray.
__global__ void k_compose(float* __restrict__ out) {
    __shared__ float s_scan[256];
    __shared__ float s_r[256], s_g[256], s_b[256];
    int ray = blockIdx.x;
    int t = threadIdx.x;
    int gs = ray * 256 + t;

    float q = 0.5f * g_sp[gs];        // INTERVAL = 0.5
    s_scan[t] = q;
    __syncthreads();
    #pragma unroll
    for (int off = 1; off < 256; off <<= 1) {
        float v = (t >= off) ? s_scan[t - off] : 0.0f;
        __syncthreads();
        s_scan[t] += v;
        __syncthreads();
    }
    float incl = s_scan[t];
    float T_excl = expf(-(incl - q));
    float alpha = 1.0f - expf(-q);
    float wgt = alpha * T_excl;

    s_r[t] = wgt * g_rgb[(size_t)gs * 3 + 0];
    s_g[t] = wgt * g_rgb[(size_t)gs * 3 + 1];
    s_b[t] = wgt * g_rgb[(size_t)gs * 3 + 2];
    __syncthreads();
    for (int off = 128; off > 0; off >>= 1) {
        if (t < off) {
            s_r[t] += s_r[t + off];
            s_g[t] += s_g[t + off];
            s_b[t] += s_b[t + off];
        }
        __syncthreads();
    }
    if (t == 0) {
        float ainv = expf(-s_scan[255]);
        out[ray * 3 + 0] = s_r[0] + ainv;
        out[ray * 3 + 1] = s_g[0] + ainv;
        out[ray * 3 + 2] = s_b[0] + ainv;
    }
}

// ---------------- launch ----------------
extern "C" void kernel_launch(void* const* d_in, const int* in_sizes, int n_in,
                              void* d_out, int out_size) {
    const float* pts      = (const float*)d_in[0];
    const float* viewdirs = (const float*)d_in[1];
    const float* dens     = (const float*)d_in[2];
    const float* k0       = (const float*)d_in[3];
    const float* w0g      = (const float*)d_in[4];
    const float* b0g      = (const float*)d_in[5];
    const float* w1g      = (const float*)d_in[6];
    const float* b1g      = (const float*)d_in[7];
    const float* w2g      = (const float*)d_in[8];
    const float* b2g      = (const float*)d_in[9];
    float* out = (float*)d_out;

    cudaFuncSetAttribute(k_mlp, cudaFuncAttributeMaxDynamicSharedMemorySize, SMEM_BYTES);

    k_transpose<<<V / 32, 512>>>(dens, k0);
    k_mlp<<<NS / TILE, 256, SMEM_BYTES>>>(pts, viewdirs, w0g, b0g, w1g, b1g, w2g, b2g);
    k_compose<<<NRAYS, 256>>>(out);
}

// round 4
// speedup vs baseline: 2.6457x; 2.6457x over previous
#include <cuda_runtime.h>
#include <cuda_bf16.h>
#include <cstdint>
#include <math.h>

// ---------------- problem constants ----------------
#define G        160
#define V        (G*G*G)          // 4,096,000 voxels
#define NRAYS    4096
#define S        256
#define NS       (NRAYS*S)        // 1,048,576 samples
#define TILE     128
#define NTILES   (NS/TILE)        // 8192
#define ACT_SHIFT (-4.5951198501345898f)   // log(0.01/0.99)

#define FSTRIDE  56               // bf16 elems/row for feat + w0 tiles (K<=48)
#define HSTRIDE  136              // bf16 elems/row for w1 tiles (K=128)

// ---------------- scratch ----------------
__device__ float g_inter[(size_t)V * 16];   // [vox][16]: ch0..11 = k0, ch12 = density
__device__ float g_sp[NS];                  // softplus(dens + shift)
__device__ float g_rgb[(size_t)NS * 3];     // per-sample rgb (post-sigmoid)

// ---------------- smem layout (byte offsets) ----------------
#define FEAT_HI_OFF 0
#define FEAT_LO_OFF (FEAT_HI_OFF + 128*FSTRIDE*2)     // 14336
#define W0HI_OFF    (FEAT_LO_OFF + 128*FSTRIDE*2)     // 28672
#define W0LO_OFF    (W0HI_OFF    + 128*FSTRIDE*2)     // 43008
#define W1HI_OFF    (W0LO_OFF    + 128*FSTRIDE*2)     // 57344
#define W1LO_OFF    (W1HI_OFF    + 128*HSTRIDE*2)     // 92160
#define B0S_OFF     (W1LO_OFF    + 128*HSTRIDE*2)     // 126976
#define B1S_OFF     (B0S_OFF + 512)
#define W2S_OFF     (B1S_OFF + 512)
#define B2S_OFF     (W2S_OFF + 128*3*4)
#define SMEM_TOTAL  (B2S_OFF + 64)

// ---------------- PTX helpers (baseline ISA only) ----------------
__device__ __forceinline__ uint32_t smem_u32(const void* p) {
    uint32_t a;
    asm("{ .reg .u64 tmp; cvta.to.shared.u64 tmp, %1; cvt.u32.u64 %0, tmp; }" : "=r"(a) : "l"(p));
    return a;
}
#define LDSM4(r, a) \
    asm volatile("ldmatrix.sync.aligned.m8n8.x4.shared.b16 {%0,%1,%2,%3}, [%4];" \
        : "=r"((r)[0]), "=r"((r)[1]), "=r"((r)[2]), "=r"((r)[3]) : "r"(a))

#define MMA16816(c, a, b0_, b1_) \
    asm volatile("mma.sync.aligned.m16n8k16.row.col.f32.bf16.bf16.f32 " \
        "{%0,%1,%2,%3}, {%4,%5,%6,%7}, {%8,%9}, {%0,%1,%2,%3};" \
        : "+f"((c)[0]), "+f"((c)[1]), "+f"((c)[2]), "+f"((c)[3]) \
        : "r"((a)[0]), "r"((a)[1]), "r"((a)[2]), "r"((a)[3]), "r"(b0_), "r"(b1_))

// bf16 hi/lo split helpers
__device__ __forceinline__ uint32_t bf16x2_hi(float a0, float a1, float& l0, float& l1) {
    uint32_t hw;
    asm("cvt.rn.satfinite.bf16x2.f32 %0, %1, %2;" : "=r"(hw) : "f"(a1), "f"(a0));  // a0 -> lower
    __nv_bfloat162 h2 = *reinterpret_cast<__nv_bfloat162*>(&hw);
    l0 = a0 - __bfloat162float(h2.x);
    l1 = a1 - __bfloat162float(h2.y);
    return hw;
}
__device__ __forceinline__ uint32_t bf16x2_pack(float a0, float a1) {
    uint32_t w;
    asm("cvt.rn.satfinite.bf16x2.f32 %0, %1, %2;" : "=r"(w) : "f"(a1), "f"(a0));
    return w;
}

// ---------------- kernel 1: transpose grids to interleaved layout ----------
__global__ __launch_bounds__(256) void k_transpose(const float* __restrict__ dens,
                                                   const float* __restrict__ k0) {
    int v = blockIdx.x * 256 + threadIdx.x;
    float r[13];
#pragma unroll
    for (int c = 0; c < 12; c++) r[c] = __ldg(k0 + (size_t)c * V + v);
    r[12] = __ldg(dens + v);
    float4* out = reinterpret_cast<float4*>(g_inter) + (size_t)v * 4;
    out[0] = make_float4(r[0], r[1], r[2], r[3]);
    out[1] = make_float4(r[4], r[5], r[6], r[7]);
    out[2] = make_float4(r[8], r[9], r[10], r[11]);
    out[3] = make_float4(r[12], 0.f, 0.f, 0.f);
}

// ---------------- kernel 2: persistent featurize + mma.sync MLP ----------------
__global__ __launch_bounds__(256, 1)
void k_mlp(const float* __restrict__ pts,
           const float* __restrict__ viewdirs,
           const float* __restrict__ w0g, const float* __restrict__ b0g,
           const float* __restrict__ w1g, const float* __restrict__ b1g,
           const float* __restrict__ w2g, const float* __restrict__ b2g) {
    extern __shared__ char sm[];
    const uint32_t sb = smem_u32(sm);
    const int t = threadIdx.x;
    const int lane = t & 31;
    const int warp = t >> 5;

    float* b0s = reinterpret_cast<float*>(sm + B0S_OFF);
    float* b1s = reinterpret_cast<float*>(sm + B1S_OFF);
    float* w2s = reinterpret_cast<float*>(sm + W2S_OFF);
    float* b2s = reinterpret_cast<float*>(sm + B2S_OFF);

    // ---- zero feat + w0 regions (K-pad stays zero forever) ----
    for (int i = t; i < W1HI_OFF / 4; i += 256)
        reinterpret_cast<uint32_t*>(sm)[i] = 0;
    __syncthreads();

    // ---- stage weights (once per block) ----
    // w0: [39][128] -> B0[n][k] = w0[k][n], hi/lo
    for (int i = t; i < 39 * 128; i += 256) {
        int k = i >> 7, n = i & 127;
        float v = w0g[i];
        __nv_bfloat16 h = __float2bfloat16(v);
        __nv_bfloat16 l = __float2bfloat16(v - __bfloat162float(h));
        reinterpret_cast<__nv_bfloat16*>(sm + W0HI_OFF)[n * FSTRIDE + k] = h;
        reinterpret_cast<__nv_bfloat16*>(sm + W0LO_OFF)[n * FSTRIDE + k] = l;
    }
    // w1: [128][128] -> B1[n][k] = w1[k][n], hi/lo
    for (int i = t; i < 128 * 128; i += 256) {
        int k = i >> 7, n = i & 127;
        float v = w1g[i];
        __nv_bfloat16 h = __float2bfloat16(v);
        __nv_bfloat16 l = __float2bfloat16(v - __bfloat162float(h));
        reinterpret_cast<__nv_bfloat16*>(sm + W1HI_OFF)[n * HSTRIDE + k] = h;
        reinterpret_cast<__nv_bfloat16*>(sm + W1LO_OFF)[n * HSTRIDE + k] = l;
    }
    if (t < 128) { b0s[t] = b0g[t]; b1s[t] = b1g[t]; }
    for (int i = t; i < 384; i += 256) w2s[i] = w2g[i];
    if (t < 3) b2s[t] = b2g[t];
    __syncthreads();

    // ---- per-lane ldmatrix address components ----
    // A-type x4 (16x16): lanes 0-7 rows0-7/k0, 8-15 rows8-15/k0, 16-23 rows0-7/k8, 24-31 rows8-15/k8
    const int a_row = (((lane >> 3) & 1) << 3) + (lane & 7);
    const int a_k8  = (lane >> 4) << 3;
    // B-type x4 (two n-tiles x 16k): lanes 0-7 n0-7/k0, 8-15 n0-7/k8, 16-23 n8-15/k0, 24-31 n8-15/k8
    const int b_row = ((lane >> 4) << 3) + (lane & 7);
    const int b_k8  = ((lane >> 3) & 1) << 3;

    const int m0 = warp << 4;          // 16 rows per warp
    const int lane4 = lane & 3;
    const int laneq = lane >> 2;

    for (int tile = blockIdx.x; tile < NTILES; tile += gridDim.x) {
        // ===== featurize: threads 0..127, sample row = t =====
        if (t < 128) {
            const int gs = tile * TILE + t;
            const int ray = tile >> 1;
            float fv[40];

            const float* pp = pts + (size_t)gs * 3;
            float f[3]; int i0[3];
#pragma unroll
            for (int d = 0; d < 3; d++) {
                float u = (pp[d] + 1.0f) * (0.5f * (G - 1));
                u = fminf(fmaxf(u, 0.0f), (float)(G - 1));
                int ii = (int)floorf(u);
                ii = min(ii, G - 2);
                f[d] = u - (float)ii;
                i0[d] = ii;
            }
            float wx[2] = {1.0f - f[0], f[0]};
            float wy[2] = {1.0f - f[1], f[1]};
            float wz[2] = {1.0f - f[2], f[2]};

            float acc[13];
#pragma unroll
            for (int c = 0; c < 13; c++) acc[c] = 0.0f;
#pragma unroll
            for (int dx = 0; dx < 2; dx++)
#pragma unroll
            for (int dy = 0; dy < 2; dy++)
#pragma unroll
            for (int dz = 0; dz < 2; dz++) {
                float wgt = wx[dx] * wy[dy] * wz[dz];
                int vox = ((i0[0] + dx) * G + (i0[1] + dy)) * G + (i0[2] + dz);
                const float4* cp = reinterpret_cast<const float4*>(g_inter) + (size_t)vox * 4;
                float4 A = cp[0], B = cp[1], Cc = cp[2], D = cp[3];
                acc[0]  += wgt * A.x;  acc[1]  += wgt * A.y;
                acc[2]  += wgt * A.z;  acc[3]  += wgt * A.w;
                acc[4]  += wgt * B.x;  acc[5]  += wgt * B.y;
                acc[6]  += wgt * B.z;  acc[7]  += wgt * B.w;
                acc[8]  += wgt * Cc.x; acc[9]  += wgt * Cc.y;
                acc[10] += wgt * Cc.z; acc[11] += wgt * Cc.w;
                acc[12] += wgt * D.x;
            }
            float dd = acc[12] + ACT_SHIFT;
            g_sp[gs] = (dd > 15.0f) ? dd : log1pf(expf(dd));

            float vx = viewdirs[ray * 3 + 0];
            float vy = viewdirs[ray * 3 + 1];
            float vz = viewdirs[ray * 3 + 2];
            float inv = rsqrtf(vx * vx + vy * vy + vz * vz);
            vx *= inv; vy *= inv; vz *= inv;
#pragma unroll
            for (int c = 0; c < 12; c++) fv[c] = acc[c];
            fv[12] = vx; fv[13] = vy; fv[14] = vz;
            float vdn[3] = {vx, vy, vz};
#pragma unroll
            for (int d = 0; d < 3; d++) {
#pragma unroll
                for (int fq = 0; fq < 4; fq++) {
                    float sv, cv;
                    sincosf(vdn[d] * (float)(1 << fq), &sv, &cv);
                    fv[15 + d * 4 + fq] = sv;
                    fv[27 + d * 4 + fq] = cv;
                }
            }
            fv[39] = 0.0f;
            // write feat row t (pairs -> u32), cols 0..39
            uint32_t* hrow = reinterpret_cast<uint32_t*>(sm + FEAT_HI_OFF + (size_t)t * FSTRIDE * 2);
            uint32_t* lrow = reinterpret_cast<uint32_t*>(sm + FEAT_LO_OFF + (size_t)t * FSTRIDE * 2);
#pragma unroll
            for (int j = 0; j < 20; j++) {
                float l0, l1;
                uint32_t hw = bf16x2_hi(fv[2 * j], fv[2 * j + 1], l0, l1);
                hrow[j] = hw;
                lrow[j] = bf16x2_pack(l0, l1);
            }
        }
        __syncthreads();

        // ===== GEMM1: c[128x128] = feat @ w0^T + b0 (3-term bf16) =====
        float c[16][4];
#pragma unroll
        for (int j = 0; j < 16; j++) {
            int col0 = 8 * j + 2 * lane4;
            c[j][0] = b0s[col0]; c[j][1] = b0s[col0 + 1];
            c[j][2] = c[j][0];   c[j][3] = c[j][1];
        }
        uint32_t ah[3][4], al[3][4];
#pragma unroll
        for (int tk = 0; tk < 3; tk++) {
            LDSM4(ah[tk], sb + FEAT_HI_OFF + ((m0 + a_row) * FSTRIDE + tk * 16 + a_k8) * 2);
            LDSM4(al[tk], sb + FEAT_LO_OFF + ((m0 + a_row) * FSTRIDE + tk * 16 + a_k8) * 2);
        }
#pragma unroll
        for (int tk = 0; tk < 3; tk++) {
#pragma unroll
            for (int g = 0; g < 8; g++) {
                uint32_t bh[4], bl[4];
                uint32_t boff = ((16 * g + b_row) * FSTRIDE + tk * 16 + b_k8) * 2;
                LDSM4(bh, sb + W0HI_OFF + boff);
                MMA16816(c[2 * g],     ah[tk], bh[0], bh[1]);
                MMA16816(c[2 * g + 1], ah[tk], bh[2], bh[3]);
                MMA16816(c[2 * g],     al[tk], bh[0], bh[1]);
                MMA16816(c[2 * g + 1], al[tk], bh[2], bh[3]);
                LDSM4(bl, sb + W0LO_OFF + boff);
                MMA16816(c[2 * g],     ah[tk], bl[0], bl[1]);
                MMA16816(c[2 * g + 1], ah[tk], bl[2], bl[3]);
            }
        }

        // ===== epilogue1: relu -> bf16 hi/lo A-fragments for GEMM2 (in regs) =====
        uint32_t a2h[8][4], a2l[8][4];
#pragma unroll
        for (int j = 0; j < 16; j++)
#pragma unroll
            for (int q = 0; q < 4; q++) c[j][q] = fmaxf(c[j][q], 0.0f);
#pragma unroll
        for (int tk = 0; tk < 8; tk++) {
            float l0, l1;
            a2h[tk][0] = bf16x2_hi(c[2 * tk][0],     c[2 * tk][1],     l0, l1); a2l[tk][0] = bf16x2_pack(l0, l1);
            a2h[tk][1] = bf16x2_hi(c[2 * tk][2],     c[2 * tk][3],     l0, l1); a2l[tk][1] = bf16x2_pack(l0, l1);
            a2h[tk][2] = bf16x2_hi(c[2 * tk + 1][0], c[2 * tk + 1][1], l0, l1); a2l[tk][2] = bf16x2_pack(l0, l1);
            a2h[tk][3] = bf16x2_hi(c[2 * tk + 1][2], c[2 * tk + 1][3], l0, l1); a2l[tk][3] = bf16x2_pack(l0, l1);
        }

        // ===== GEMM2: d = relu(h1) @ w1^T + b1 (3-term) =====
        float d[16][4];
#pragma unroll
        for (int j = 0; j < 16; j++) {
            int col0 = 8 * j + 2 * lane4;
            d[j][0] = b1s[col0]; d[j][1] = b1s[col0 + 1];
            d[j][2] = d[j][0];   d[j][3] = d[j][1];
        }
#pragma unroll
        for (int tk = 0; tk < 8; tk++) {
#pragma unroll
            for (int g = 0; g < 8; g++) {
                uint32_t wh[4], wl[4];
                uint32_t boff = ((16 * g + b_row) * HSTRIDE + tk * 16 + b_k8) * 2;
                LDSM4(wh, sb + W1HI_OFF + boff);
                MMA16816(d[2 * g],     a2h[tk], wh[0], wh[1]);
                MMA16816(d[2 * g + 1], a2h[tk], wh[2], wh[3]);
                MMA16816(d[2 * g],     a2l[tk], wh[0], wh[1]);
                MMA16816(d[2 * g + 1], a2l[tk], wh[2], wh[3]);
                LDSM4(wl, sb + W1LO_OFF + boff);
                MMA16816(d[2 * g],     a2h[tk], wl[0], wl[1]);
                MMA16816(d[2 * g + 1], a2h[tk], wl[2], wl[3]);
            }
        }

        // ===== epilogue2: rgb = sigmoid(relu(d) @ w2 + b2) =====
        {
            float p00 = 0.f, p01 = 0.f, p02 = 0.f;   // row laneq
            float p10 = 0.f, p11 = 0.f, p12 = 0.f;   // row laneq+8
#pragma unroll
            for (int j = 0; j < 16; j++) {
                int col0 = 8 * j + 2 * lane4;
                float h00 = fmaxf(d[j][0], 0.f), h01 = fmaxf(d[j][1], 0.f);
                float h10 = fmaxf(d[j][2], 0.f), h11 = fmaxf(d[j][3], 0.f);
                const float* wA = w2s + col0 * 3;
                const float* wB = w2s + (col0 + 1) * 3;
                p00 += h00 * wA[0] + h01 * wB[0];
                p01 += h00 * wA[1] + h01 * wB[1];
                p02 += h00 * wA[2] + h01 * wB[2];
                p10 += h10 * wA[0] + h11 * wB[0];
                p11 += h10 * wA[1] + h11 * wB[1];
                p12 += h10 * wA[2] + h11 * wB[2];
            }
#pragma unroll
            for (int sh = 1; sh <= 2; sh <<= 1) {
                p00 += __shfl_xor_sync(0xffffffffu, p00, sh);
                p01 += __shfl_xor_sync(0xffffffffu, p01, sh);
                p02 += __shfl_xor_sync(0xffffffffu, p02, sh);
                p10 += __shfl_xor_sync(0xffffffffu, p10, sh);
                p11 += __shfl_xor_sync(0xffffffffu, p11, sh);
                p12 += __shfl_xor_sync(0xffffffffu, p12, sh);
            }
            if (lane4 == 0) {
                int gs0 = tile * TILE + m0 + laneq;
                int gs1 = gs0 + 8;
                g_rgb[(size_t)gs0 * 3 + 0] = 1.0f / (1.0f + expf(-(p00 + b2s[0])));
                g_rgb[(size_t)gs0 * 3 + 1] = 1.0f / (1.0f + expf(-(p01 + b2s[1])));
                g_rgb[(size_t)gs0 * 3 + 2] = 1.0f / (1.0f + expf(-(p02 + b2s[2])));
                g_rgb[(size_t)gs1 * 3 + 0] = 1.0f / (1.0f + expf(-(p10 + b2s[0])));
                g_rgb[(size_t)gs1 * 3 + 1] = 1.0f / (1.0f + expf(-(p11 + b2s[1])));
                g_rgb[(size_t)gs1 * 3 + 2] = 1.0f / (1.0f + expf(-(p12 + b2s[2])));
            }
        }
        __syncthreads();
    }
}

// ---------------- kernel 3: per-ray composite ----------------
__global__ void k_compose(float* __restrict__ out) {
    __shared__ float s_scan[256];
    __shared__ float s_r[256], s_g[256], s_b[256];
    int ray = blockIdx.x;
    int t = threadIdx.x;
    int gs = ray * 256 + t;

    float q = 0.5f * g_sp[gs];
    s_scan[t] = q;
    __syncthreads();
#pragma unroll
    for (int off = 1; off < 256; off <<= 1) {
        float v = (t >= off) ? s_scan[t - off] : 0.0f;
        __syncthreads();
        s_scan[t] += v;
        __syncthreads();
    }
    float incl = s_scan[t];
    float T_excl = expf(-(incl - q));
    float alpha = 1.0f - expf(-q);
    float wgt = alpha * T_excl;

    s_r[t] = wgt * g_rgb[(size_t)gs * 3 + 0];
    s_g[t] = wgt * g_rgb[(size_t)gs * 3 + 1];
    s_b[t] = wgt * g_rgb[(size_t)gs * 3 + 2];
    __syncthreads();
    for (int off = 128; off > 0; off >>= 1) {
        if (t < off) {
            s_r[t] += s_r[t + off];
            s_g[t] += s_g[t + off];
            s_b[t] += s_b[t + off];
        }
        __syncthreads();
    }
    if (t == 0) {
        float ainv = expf(-s_scan[255]);
        out[ray * 3 + 0] = s_r[0] + ainv;
        out[ray * 3 + 1] = s_g[0] + ainv;
        out[ray * 3 + 2] = s_b[0] + ainv;
    }
}

// ---------------- launch ----------------
extern "C" void kernel_launch(void* const* d_in, const int* in_sizes, int n_in,
                              void* d_out, int out_size) {
    const float* pts      = (const float*)d_in[0];
    const float* viewdirs = (const float*)d_in[1];
    const float* dens     = (const float*)d_in[2];
    const float* k0       = (const float*)d_in[3];
    const float* w0g      = (const float*)d_in[4];
    const float* b0g      = (const float*)d_in[5];
    const float* w1g      = (const float*)d_in[6];
    const float* b1g      = (const float*)d_in[7];
    const float* w2g      = (const float*)d_in[8];
    const float* b2g      = (const float*)d_in[9];
    float* out = (float*)d_out;

    cudaFuncSetAttribute(k_mlp, cudaFuncAttributeMaxDynamicSharedMemorySize, SMEM_TOTAL);

    k_transpose<<<V / 256, 256>>>(dens, k0);
    k_mlp<<<152, 256, SMEM_TOTAL>>>(pts, viewdirs, w0g, b0g, w1g, b1g, w2g, b2g);
    k_compose<<<NRAYS, 256>>>(out);
}

// round 5
// speedup vs baseline: 3.9315x; 1.4860x over previous
#include <cuda_runtime.h>
#include <cuda_fp16.h>
#include <cuda_bf16.h>
#include <cstdint>
#include <math.h>

// ---------------- problem constants ----------------
#define G        160
#define V        (G*G*G)          // 4,096,000 voxels
#define NRAYS    4096
#define S        256
#define NS       (NRAYS*S)        // 1,048,576 samples
#define TILE     128
#define NTILES   (NS/TILE)        // 8192
#define ACT_SHIFT (-4.5951198501345898f)   // log(0.01/0.99)

#define FSTR     24               // fp16 elems/row, feat + w0 tiles (K=16 +pad)
#define HSTR     136              // fp16 elems/row, w1 tiles (K=128 +pad)

// ---------------- scratch ----------------
__device__ float g_inter[(size_t)V * 16];   // [vox][16]: ch0..11 = k0, ch12 = density
__device__ float g_sp[NS];                  // softplus(dens + shift)
__device__ float g_rgb[(size_t)NS * 3];     // per-sample rgb (post-sigmoid)
__device__ float g_b0r[(size_t)NRAYS * 128];// per-ray fused bias: b0 + emb@w0[12:39]

// ---------------- smem layout (byte offsets) ----------------
#define FEAT_OFF  0
#define W0HI_OFF  (FEAT_OFF + 128*FSTR*2)     // 6144
#define W0LO_OFF  (W0HI_OFF + 128*FSTR*2)     // 12288
#define W1HI_OFF  (W0LO_OFF + 128*FSTR*2)     // 18432
#define W1LO_OFF  (W1HI_OFF + 128*HSTR*2)     // 53248
#define PSUM_OFF  (W1LO_OFF + 128*HSTR*2)     // 88064  (128 x 14 f32)
#define B1S_OFF   (PSUM_OFF + 128*14*4)       // 95232
#define W2S_OFF   (B1S_OFF + 512)             // 95744
#define B2S_OFF   (W2S_OFF + 128*3*4)         // 97280
#define SMEM_TOTAL (B2S_OFF + 64)

// ---------------- PTX helpers (baseline ISA only) ----------------
__device__ __forceinline__ uint32_t smem_u32(const void* p) {
    uint32_t a;
    asm("{ .reg .u64 tmp; cvta.to.shared.u64 tmp, %1; cvt.u32.u64 %0, tmp; }" : "=r"(a) : "l"(p));
    return a;
}
#define LDSM4(r, a) \
    asm volatile("ldmatrix.sync.aligned.m8n8.x4.shared.b16 {%0,%1,%2,%3}, [%4];" \
        : "=r"((r)[0]), "=r"((r)[1]), "=r"((r)[2]), "=r"((r)[3]) : "r"(a))

#define MMA16816(c, a, b0_, b1_) \
    asm volatile("mma.sync.aligned.m16n8k16.row.col.f32.f16.f16.f32 " \
        "{%0,%1,%2,%3}, {%4,%5,%6,%7}, {%8,%9}, {%0,%1,%2,%3};" \
        : "+f"((c)[0]), "+f"((c)[1]), "+f"((c)[2]), "+f"((c)[3]) \
        : "r"((a)[0]), "r"((a)[1]), "r"((a)[2]), "r"((a)[3]), "r"(b0_), "r"(b1_))

__device__ __forceinline__ uint32_t h2pack(float lo, float hi) {
    __half2 h = __floats2half2_rn(lo, hi);     // .x = lo (low 16 bits)
    return *reinterpret_cast<uint32_t*>(&h);
}

// ---------------- kernel 0: per-ray fused bias ----------------
__global__ __launch_bounds__(128) void k_raybias(const float* __restrict__ vdirs,
                                                 const float* __restrict__ w0g,
                                                 const float* __restrict__ b0g) {
    __shared__ float emb[28];
    const int ray = blockIdx.x;
    const int t = threadIdx.x;
    float vx = __ldg(vdirs + ray * 3 + 0);
    float vy = __ldg(vdirs + ray * 3 + 1);
    float vz = __ldg(vdirs + ray * 3 + 2);
    float inv = rsqrtf(vx * vx + vy * vy + vz * vz);
    vx *= inv; vy *= inv; vz *= inv;
    if (t < 27) {
        if (t < 3) {
            emb[t] = (t == 0) ? vx : (t == 1) ? vy : vz;
        } else if (t < 15) {
            int i = t - 3, d = i >> 2, f = i & 3;
            float v = (d == 0) ? vx : (d == 1) ? vy : vz;
            emb[t] = sinf(v * (float)(1 << f));
        } else {
            int i = t - 15, d = i >> 2, f = i & 3;
            float v = (d == 0) ? vx : (d == 1) ? vy : vz;
            emb[t] = cosf(v * (float)(1 << f));
        }
    }
    __syncthreads();
    float s = b0g[t];
#pragma unroll
    for (int e = 0; e < 27; e++) s += emb[e] * w0g[(12 + e) * 128 + t];
    g_b0r[(size_t)ray * 128 + t] = s;
}

// ---------------- kernel 1: transpose grids to interleaved layout ----------
__global__ __launch_bounds__(256) void k_transpose(const float* __restrict__ dens,
                                                   const float* __restrict__ k0) {
    int v = blockIdx.x * 256 + threadIdx.x;
    float r[13];
#pragma unroll
    for (int c = 0; c < 12; c++) r[c] = __ldg(k0 + (size_t)c * V + v);
    r[12] = __ldg(dens + v);
    float4* out = reinterpret_cast<float4*>(g_inter) + (size_t)v * 4;
    out[0] = make_float4(r[0], r[1], r[2], r[3]);
    out[1] = make_float4(r[4], r[5], r[6], r[7]);
    out[2] = make_float4(r[8], r[9], r[10], r[11]);
    out[3] = make_float4(r[12], 0.f, 0.f, 0.f);
}

// ---------------- kernel 2: persistent featurize + fp16 mma MLP ----------------
__global__ __launch_bounds__(256, 2)
void k_mlp(const float* __restrict__ pts,
           const float* __restrict__ w0g,
           const float* __restrict__ w1g, const float* __restrict__ b1g,
           const float* __restrict__ w2g, const float* __restrict__ b2g) {
    extern __shared__ char sm[];
    const uint32_t sb = smem_u32(sm);
    const int t = threadIdx.x;
    const int lane = t & 31;
    const int warp = t >> 5;

    float* psum = reinterpret_cast<float*>(sm + PSUM_OFF);
    float* b1s  = reinterpret_cast<float*>(sm + B1S_OFF);
    float* w2s  = reinterpret_cast<float*>(sm + W2S_OFF);
    float* b2s  = reinterpret_cast<float*>(sm + B2S_OFF);

    // ---- zero feat + w0 regions (K pads stay zero) ----
    for (int i = t; i < W1HI_OFF / 4; i += 256)
        reinterpret_cast<uint32_t*>(sm)[i] = 0;
    __syncthreads();

    // ---- stage weights (once per block) ----
    // w0 rows 0..11 (k0 part): B0[n][k] = w0[k][n], fp16 hi/lo
    for (int i = t; i < 12 * 128; i += 256) {
        int k = i >> 7, n = i & 127;
        float v = w0g[i];
        __half h = __float2half_rn(v);
        __half l = __float2half_rn(v - __half2float(h));
        reinterpret_cast<__half*>(sm + W0HI_OFF)[n * FSTR + k] = h;
        reinterpret_cast<__half*>(sm + W0LO_OFF)[n * FSTR + k] = l;
    }
    // w1: [128][128] -> B1[n][k] = w1[k][n], fp16 hi/lo
    for (int i = t; i < 128 * 128; i += 256) {
        int k = i >> 7, n = i & 127;
        float v = w1g[i];
        __half h = __float2half_rn(v);
        __half l = __float2half_rn(v - __half2float(h));
        reinterpret_cast<__half*>(sm + W1HI_OFF)[n * HSTR + k] = h;
        reinterpret_cast<__half*>(sm + W1LO_OFF)[n * HSTR + k] = l;
    }
    if (t < 128) b1s[t] = b1g[t];
    for (int i = t; i < 384; i += 256) w2s[i] = w2g[i];
    if (t < 3) b2s[t] = b2g[t];
    __syncthreads();

    // ---- ldmatrix lane addressing (empirically validated in bf16 round) ----
    const int a_row = (((lane >> 3) & 1) << 3) + (lane & 7);
    const int a_k8  = (lane >> 4) << 3;
    const int b_row = ((lane >> 4) << 3) + (lane & 7);
    const int b_k8  = ((lane >> 3) & 1) << 3;

    const int m0 = warp << 4;
    const int lane4 = lane & 3;
    const int laneq = lane >> 2;

    const int s_id = t & 127;      // sample within tile
    const int half = t >> 7;       // corner-half for featurize

    for (int tile = blockIdx.x; tile < NTILES; tile += gridDim.x) {
        const int gs = tile * TILE + s_id;

        // ===== featurize: 2 threads per sample (dx = half) =====
        float acc[13];
        {
            const float* pp = pts + (size_t)gs * 3;
            float f[3]; int i0[3];
#pragma unroll
            for (int d = 0; d < 3; d++) {
                float u = (pp[d] + 1.0f) * (0.5f * (G - 1));
                u = fminf(fmaxf(u, 0.0f), (float)(G - 1));
                int ii = (int)floorf(u);
                ii = min(ii, G - 2);
                f[d] = u - (float)ii;
                i0[d] = ii;
            }
            float wxh = half ? f[0] : (1.0f - f[0]);
            float wy[2] = {1.0f - f[1], f[1]};
            float wz[2] = {1.0f - f[2], f[2]};
#pragma unroll
            for (int c = 0; c < 13; c++) acc[c] = 0.0f;
            const int xbase = ((i0[0] + half) * G + i0[1]) * G + i0[2];
#pragma unroll
            for (int dy = 0; dy < 2; dy++)
#pragma unroll
            for (int dz = 0; dz < 2; dz++) {
                float wgt = wxh * wy[dy] * wz[dz];
                int vox = xbase + dy * G + dz;
                const float4* cp = reinterpret_cast<const float4*>(g_inter) + (size_t)vox * 4;
                float4 A = cp[0], B = cp[1], Cc = cp[2], D = cp[3];
                acc[0]  += wgt * A.x;  acc[1]  += wgt * A.y;
                acc[2]  += wgt * A.z;  acc[3]  += wgt * A.w;
                acc[4]  += wgt * B.x;  acc[5]  += wgt * B.y;
                acc[6]  += wgt * B.z;  acc[7]  += wgt * B.w;
                acc[8]  += wgt * Cc.x; acc[9]  += wgt * Cc.y;
                acc[10] += wgt * Cc.z; acc[11] += wgt * Cc.w;
                acc[12] += wgt * D.x;
            }
        }
        if (half) {
#pragma unroll
            for (int c = 0; c < 13; c++) psum[s_id * 14 + c] = acc[c];
        }
        __syncthreads();
        if (!half) {
#pragma unroll
            for (int c = 0; c < 13; c++) acc[c] += psum[s_id * 14 + c];
            float dd = acc[12] + ACT_SHIFT;
            g_sp[gs] = (dd > 15.0f) ? dd : log1pf(expf(dd));
            uint32_t* frow = reinterpret_cast<uint32_t*>(sm + FEAT_OFF + (size_t)s_id * FSTR * 2);
#pragma unroll
            for (int j = 0; j < 6; j++) frow[j] = h2pack(acc[2 * j], acc[2 * j + 1]);
        }
        __syncthreads();

        // ===== GEMM1: c = feat(k0) @ w0[0:12]^T + b0r  (fp16 2-term, K=16) =====
        float c[16][4];
        {
            const float* br = g_b0r + (size_t)(tile >> 1) * 128;
#pragma unroll
            for (int j = 0; j < 16; j++) {
                float2 bb = *reinterpret_cast<const float2*>(br + 8 * j + 2 * lane4);
                c[j][0] = bb.x; c[j][1] = bb.y;
                c[j][2] = bb.x; c[j][3] = bb.y;
            }
        }
        {
            uint32_t ah[4];
            LDSM4(ah, sb + FEAT_OFF + ((m0 + a_row) * FSTR + a_k8) * 2);
#pragma unroll
            for (int g = 0; g < 8; g++) {
                uint32_t bh[4], bl[4];
                uint32_t boff = ((16 * g + b_row) * FSTR + b_k8) * 2;
                LDSM4(bh, sb + W0HI_OFF + boff);
                MMA16816(c[2 * g],     ah, bh[0], bh[1]);
                MMA16816(c[2 * g + 1], ah, bh[2], bh[3]);
                LDSM4(bl, sb + W0LO_OFF + boff);
                MMA16816(c[2 * g],     ah, bl[0], bl[1]);
                MMA16816(c[2 * g + 1], ah, bl[2], bl[3]);
            }
        }

        // ===== epilogue1: relu -> fp16 A-fragments (in regs) =====
        uint32_t a2[8][4];
#pragma unroll
        for (int tk = 0; tk < 8; tk++) {
            a2[tk][0] = h2pack(fmaxf(c[2 * tk][0], 0.f),     fmaxf(c[2 * tk][1], 0.f));
            a2[tk][1] = h2pack(fmaxf(c[2 * tk][2], 0.f),     fmaxf(c[2 * tk][3], 0.f));
            a2[tk][2] = h2pack(fmaxf(c[2 * tk + 1][0], 0.f), fmaxf(c[2 * tk + 1][1], 0.f));
            a2[tk][3] = h2pack(fmaxf(c[2 * tk + 1][2], 0.f), fmaxf(c[2 * tk + 1][3], 0.f));
        }

        // ===== GEMM2: d = h1 @ w1^T + b1  (fp16 2-term on W, K=128) =====
        float d[16][4];
#pragma unroll
        for (int j = 0; j < 16; j++) {
            int col0 = 8 * j + 2 * lane4;
            d[j][0] = b1s[col0]; d[j][1] = b1s[col0 + 1];
            d[j][2] = d[j][0];   d[j][3] = d[j][1];
        }
#pragma unroll
        for (int tk = 0; tk < 8; tk++) {
#pragma unroll
            for (int g = 0; g < 8; g++) {
                uint32_t wh[4], wl[4];
                uint32_t boff = ((16 * g + b_row) * HSTR + tk * 16 + b_k8) * 2;
                LDSM4(wh, sb + W1HI_OFF + boff);
                MMA16816(d[2 * g],     a2[tk], wh[0], wh[1]);
                MMA16816(d[2 * g + 1], a2[tk], wh[2], wh[3]);
                LDSM4(wl, sb + W1LO_OFF + boff);
                MMA16816(d[2 * g],     a2[tk], wl[0], wl[1]);
                MMA16816(d[2 * g + 1], a2[tk], wl[2], wl[3]);
            }
        }

        // ===== epilogue2: rgb = sigmoid(relu(d) @ w2 + b2) =====
        {
            float p00 = 0.f, p01 = 0.f, p02 = 0.f;
            float p10 = 0.f, p11 = 0.f, p12 = 0.f;
#pragma unroll
            for (int j = 0; j < 16; j++) {
                int col0 = 8 * j + 2 * lane4;
                float h00 = fmaxf(d[j][0], 0.f), h01 = fmaxf(d[j][1], 0.f);
                float h10 = fmaxf(d[j][2], 0.f), h11 = fmaxf(d[j][3], 0.f);
                const float* wA = w2s + col0 * 3;
                const float* wB = w2s + (col0 + 1) * 3;
                p00 += h00 * wA[0] + h01 * wB[0];
                p01 += h00 * wA[1] + h01 * wB[1];
                p02 += h00 * wA[2] + h01 * wB[2];
                p10 += h10 * wA[0] + h11 * wB[0];
                p11 += h10 * wA[1] + h11 * wB[1];
                p12 += h10 * wA[2] + h11 * wB[2];
            }
#pragma unroll
            for (int sh = 1; sh <= 2; sh <<= 1) {
                p00 += __shfl_xor_sync(0xffffffffu, p00, sh);
                p01 += __shfl_xor_sync(0xffffffffu, p01, sh);
                p02 += __shfl_xor_sync(0xffffffffu, p02, sh);
                p10 += __shfl_xor_sync(0xffffffffu, p10, sh);
                p11 += __shfl_xor_sync(0xffffffffu, p11, sh);
                p12 += __shfl_xor_sync(0xffffffffu, p12, sh);
            }
            if (lane4 == 0) {
                int gs0 = tile * TILE + m0 + laneq;
                int gs1 = gs0 + 8;
                g_rgb[(size_t)gs0 * 3 + 0] = 1.0f / (1.0f + expf(-(p00 + b2s[0])));
                g_rgb[(size_t)gs0 * 3 + 1] = 1.0f / (1.0f + expf(-(p01 + b2s[1])));
                g_rgb[(size_t)gs0 * 3 + 2] = 1.0f / (1.0f + expf(-(p02 + b2s[2])));
                g_rgb[(size_t)gs1 * 3 + 0] = 1.0f / (1.0f + expf(-(p10 + b2s[0])));
                g_rgb[(size_t)gs1 * 3 + 1] = 1.0f / (1.0f + expf(-(p11 + b2s[1])));
                g_rgb[(size_t)gs1 * 3 + 2] = 1.0f / (1.0f + expf(-(p12 + b2s[2])));
            }
        }
        __syncthreads();
    }
}

// ---------------- kernel 3: per-ray composite ----------------
__global__ void k_compose(float* __restrict__ out) {
    __shared__ float s_scan[256];
    __shared__ float s_r[256], s_g[256], s_b[256];
    int ray = blockIdx.x;
    int t = threadIdx.x;
    int gs = ray * 256 + t;

    float q = 0.5f * g_sp[gs];
    s_scan[t] = q;
    __syncthreads();
#pragma unroll
    for (int off = 1; off < 256; off <<= 1) {
        float v = (t >= off) ? s_scan[t - off] : 0.0f;
        __syncthreads();
        s_scan[t] += v;
        __syncthreads();
    }
    float incl = s_scan[t];
    float T_excl = expf(-(incl - q));
    float alpha = 1.0f - expf(-q);
    float wgt = alpha * T_excl;

    s_r[t] = wgt * g_rgb[(size_t)gs * 3 + 0];
    s_g[t] = wgt * g_rgb[(size_t)gs * 3 + 1];
    s_b[t] = wgt * g_rgb[(size_t)gs * 3 + 2];
    __syncthreads();
    for (int off = 128; off > 0; off >>= 1) {
        if (t < off) {
            s_r[t] += s_r[t + off];
            s_g[t] += s_g[t + off];
            s_b[t] += s_b[t + off];
        }
        __syncthreads();
    }
    if (t == 0) {
        float ainv = expf(-s_scan[255]);
        out[ray * 3 + 0] = s_r[0] + ainv;
        out[ray * 3 + 1] = s_g[0] + ainv;
        out[ray * 3 + 2] = s_b[0] + ainv;
    }
}

// ---------------- launch ----------------
extern "C" void kernel_launch(void* const* d_in, const int* in_sizes, int n_in,
                              void* d_out, int out_size) {
    const float* pts      = (const float*)d_in[0];
    const float* viewdirs = (const float*)d_in[1];
    const float* dens     = (const float*)d_in[2];
    const float* k0       = (const float*)d_in[3];
    const float* w0g      = (const float*)d_in[4];
    const float* b0g      = (const float*)d_in[5];
    const float* w1g      = (const float*)d_in[6];
    const float* b1g      = (const float*)d_in[7];
    const float* w2g      = (const float*)d_in[8];
    const float* b2g      = (const float*)d_in[9];
    float* out = (float*)d_out;

    cudaFuncSetAttribute(k_mlp, cudaFuncAttributeMaxDynamicSharedMemorySize, SMEM_TOTAL);

    k_raybias<<<NRAYS, 128>>>(viewdirs, w0g, b0g);
    k_transpose<<<V / 256, 256>>>(dens, k0);
    k_mlp<<<304, 256, SMEM_TOTAL>>>(pts, w0g, w1g, b1g, w2g, b2g);
    k_compose<<<NRAYS, 256>>>(out);
}

// round 6
// speedup vs baseline: 5.8354x; 1.4843x over previous
#include <cuda_runtime.h>
#include <cuda_fp16.h>
#include <cstdint>
#include <math.h>

// ---------------- problem constants ----------------
#define G        160
#define V        (G*G*G)          // 4,096,000 voxels
#define NRAYS    4096
#define S        256
#define NS       (NRAYS*S)        // 1,048,576 samples
#define TILE     128
#define NTILES   (NS/TILE)        // 8192
#define ACT_SHIFT (-4.5951198501345898f)   // log(0.01/0.99)

#define FSTR     24               // fp16 elems/row, feat + w0 tiles (K=16 incl pad)
#define HSTR     136              // fp16 elems/row, w1 tiles (K=128 +pad)

// ---------------- scratch ----------------
// packed voxel: bytes 0-23 = ch0..11 fp16, bytes 24-27 = density fp32, 28-31 pad
__device__ uint4 g_pack[(size_t)V * 2];
__device__ float g_sp[NS];                  // softplus(dens + shift)
__device__ float g_rgb[(size_t)NS * 3];     // per-sample rgb (post-sigmoid)
__device__ float g_b0r[(size_t)NRAYS * 128];// per-ray fused bias: b0 + emb@w0[12:39]

// ---------------- smem layout (byte offsets) ----------------
#define FEAT_OFF  0
#define W0_OFF    (FEAT_OFF + 128*FSTR*2)     // 6144
#define W1_OFF    (W0_OFF   + 128*FSTR*2)     // 12288
#define PSUM_OFF  (W1_OFF   + 128*HSTR*2)     // 47104  (128 x 14 f32)
#define B1S_OFF   (PSUM_OFF + 128*14*4)       // 54272
#define W2S_OFF   (B1S_OFF + 512)             // 54784
#define B2S_OFF   (W2S_OFF + 128*3*4)         // 56320
#define SMEM_TOTAL (B2S_OFF + 64)

// ---------------- PTX helpers (baseline ISA only) ----------------
__device__ __forceinline__ uint32_t smem_u32(const void* p) {
    uint32_t a;
    asm("{ .reg .u64 tmp; cvta.to.shared.u64 tmp, %1; cvt.u32.u64 %0, tmp; }" : "=r"(a) : "l"(p));
    return a;
}
#define LDSM4(r, a) \
    asm volatile("ldmatrix.sync.aligned.m8n8.x4.shared.b16 {%0,%1,%2,%3}, [%4];" \
        : "=r"((r)[0]), "=r"((r)[1]), "=r"((r)[2]), "=r"((r)[3]) : "r"(a))

#define MMA16816(c, a, b0_, b1_) \
    asm volatile("mma.sync.aligned.m16n8k16.row.col.f32.f16.f16.f32 " \
        "{%0,%1,%2,%3}, {%4,%5,%6,%7}, {%8,%9}, {%0,%1,%2,%3};" \
        : "+f"((c)[0]), "+f"((c)[1]), "+f"((c)[2]), "+f"((c)[3]) \
        : "r"((a)[0]), "r"((a)[1]), "r"((a)[2]), "r"((a)[3]), "r"(b0_), "r"(b1_))

__device__ __forceinline__ uint32_t h2pack(float lo, float hi) {
    __half2 h = __floats2half2_rn(lo, hi);     // .x = lo (low 16 bits)
    return *reinterpret_cast<uint32_t*>(&h);
}
__device__ __forceinline__ float2 h2unpack(uint32_t w) {
    return __half22float2(*reinterpret_cast<__half2*>(&w));
}

// ---------------- kernel 0: per-ray fused bias ----------------
__global__ __launch_bounds__(128) void k_raybias(const float* __restrict__ vdirs,
                                                 const float* __restrict__ w0g,
                                                 const float* __restrict__ b0g) {
    __shared__ float emb[28];
    const int ray = blockIdx.x;
    const int t = threadIdx.x;
    float vx = __ldg(vdirs + ray * 3 + 0);
    float vy = __ldg(vdirs + ray * 3 + 1);
    float vz = __ldg(vdirs + ray * 3 + 2);
    float inv = rsqrtf(vx * vx + vy * vy + vz * vz);
    vx *= inv; vy *= inv; vz *= inv;
    if (t < 27) {
        if (t < 3) {
            emb[t] = (t == 0) ? vx : (t == 1) ? vy : vz;
        } else if (t < 15) {
            int i = t - 3, d = i >> 2, f = i & 3;
            float v = (d == 0) ? vx : (d == 1) ? vy : vz;
            emb[t] = sinf(v * (float)(1 << f));
        } else {
            int i = t - 15, d = i >> 2, f = i & 3;
            float v = (d == 0) ? vx : (d == 1) ? vy : vz;
            emb[t] = cosf(v * (float)(1 << f));
        }
    }
    __syncthreads();
    float s = b0g[t];
#pragma unroll
    for (int e = 0; e < 27; e++) s += emb[e] * w0g[(12 + e) * 128 + t];
    g_b0r[(size_t)ray * 128 + t] = s;
}

// ---------------- kernel 1: transpose + fp16-pack grids ----------
__global__ __launch_bounds__(256) void k_transpose(const float* __restrict__ dens,
                                                   const float* __restrict__ k0) {
    int v = blockIdx.x * 256 + threadIdx.x;
    uint32_t h[6];
#pragma unroll
    for (int j = 0; j < 6; j++) {
        float a = __ldg(k0 + (size_t)(2 * j) * V + v);
        float b = __ldg(k0 + (size_t)(2 * j + 1) * V + v);
        h[j] = h2pack(a, b);
    }
    float dd = __ldg(dens + v);
    uint4* out = g_pack + (size_t)v * 2;
    out[0] = make_uint4(h[0], h[1], h[2], h[3]);
    out[1] = make_uint4(h[4], h[5], __float_as_uint(dd), 0u);
}

// ---------------- kernel 2: persistent featurize + fp16 mma MLP ----------------
__global__ __launch_bounds__(256, 2)
void k_mlp(const float* __restrict__ pts,
           const float* __restrict__ w0g,
           const float* __restrict__ w1g, const float* __restrict__ b1g,
           const float* __restrict__ w2g, const float* __restrict__ b2g) {
    extern __shared__ char sm[];
    const uint32_t sb = smem_u32(sm);
    const int t = threadIdx.x;
    const int lane = t & 31;
    const int warp = t >> 5;

    float* psum = reinterpret_cast<float*>(sm + PSUM_OFF);
    float* b1s  = reinterpret_cast<float*>(sm + B1S_OFF);
    float* w2s  = reinterpret_cast<float*>(sm + W2S_OFF);
    float* b2s  = reinterpret_cast<float*>(sm + B2S_OFF);

    // ---- zero feat + w0 regions (K pads stay zero) ----
    for (int i = t; i < W1_OFF / 4; i += 256)
        reinterpret_cast<uint32_t*>(sm)[i] = 0;
    __syncthreads();

    // ---- stage weights (single fp16, once per block) ----
    for (int i = t; i < 12 * 128; i += 256) {
        int k = i >> 7, n = i & 127;
        reinterpret_cast<__half*>(sm + W0_OFF)[n * FSTR + k] = __float2half_rn(w0g[i]);
    }
    for (int i = t; i < 128 * 128; i += 256) {
        int k = i >> 7, n = i & 127;
        reinterpret_cast<__half*>(sm + W1_OFF)[n * HSTR + k] = __float2half_rn(w1g[i]);
    }
    if (t < 128) b1s[t] = b1g[t];
    for (int i = t; i < 384; i += 256) w2s[i] = w2g[i];
    if (t < 3) b2s[t] = b2g[t];
    __syncthreads();

    // ---- ldmatrix lane addressing ----
    const int a_row = (((lane >> 3) & 1) << 3) + (lane & 7);
    const int a_k8  = (lane >> 4) << 3;
    const int b_row = ((lane >> 4) << 3) + (lane & 7);
    const int b_k8  = ((lane >> 3) & 1) << 3;

    const int m0 = warp << 4;
    const int lane4 = lane & 3;
    const int laneq = lane >> 2;

    const int s_id = t & 127;      // sample within tile
    const int half = t >> 7;       // corner-half for featurize

    for (int tile = blockIdx.x; tile < NTILES; tile += gridDim.x) {
        const int gs = tile * TILE + s_id;

        // ===== featurize: 2 threads per sample (dx = half) =====
        float acc[13];
        {
            const float* pp = pts + (size_t)gs * 3;
            float f[3]; int i0[3];
#pragma unroll
            for (int d = 0; d < 3; d++) {
                float u = (pp[d] + 1.0f) * (0.5f * (G - 1));
                u = fminf(fmaxf(u, 0.0f), (float)(G - 1));
                int ii = (int)floorf(u);
                ii = min(ii, G - 2);
                f[d] = u - (float)ii;
                i0[d] = ii;
            }
            float wxh = half ? f[0] : (1.0f - f[0]);
            float wy[2] = {1.0f - f[1], f[1]};
            float wz[2] = {1.0f - f[2], f[2]};
#pragma unroll
            for (int c = 0; c < 13; c++) acc[c] = 0.0f;
            const int xbase = ((i0[0] + half) * G + i0[1]) * G + i0[2];
#pragma unroll
            for (int dy = 0; dy < 2; dy++)
#pragma unroll
            for (int dz = 0; dz < 2; dz++) {
                float wgt = wxh * wy[dy] * wz[dz];
                int vox = xbase + dy * G + dz;
                const uint4* cp = g_pack + (size_t)vox * 2;
                uint4 A = cp[0], B = cp[1];
                float2 p;
                p = h2unpack(A.x); acc[0]  += wgt * p.x; acc[1]  += wgt * p.y;
                p = h2unpack(A.y); acc[2]  += wgt * p.x; acc[3]  += wgt * p.y;
                p = h2unpack(A.z); acc[4]  += wgt * p.x; acc[5]  += wgt * p.y;
                p = h2unpack(A.w); acc[6]  += wgt * p.x; acc[7]  += wgt * p.y;
                p = h2unpack(B.x); acc[8]  += wgt * p.x; acc[9]  += wgt * p.y;
                p = h2unpack(B.y); acc[10] += wgt * p.x; acc[11] += wgt * p.y;
                acc[12] += wgt * __uint_as_float(B.z);
            }
        }
        if (half) {
#pragma unroll
            for (int c = 0; c < 13; c++) psum[s_id * 14 + c] = acc[c];
        }
        __syncthreads();
        if (!half) {
#pragma unroll
            for (int c = 0; c < 13; c++) acc[c] += psum[s_id * 14 + c];
            float dd = acc[12] + ACT_SHIFT;
            g_sp[gs] = (dd > 15.0f) ? dd : log1pf(expf(dd));
            uint32_t* frow = reinterpret_cast<uint32_t*>(sm + FEAT_OFF + (size_t)s_id * FSTR * 2);
#pragma unroll
            for (int j = 0; j < 6; j++) frow[j] = h2pack(acc[2 * j], acc[2 * j + 1]);
        }
        __syncthreads();

        // ===== GEMM1: c = feat(k0) @ w0[0:12]^T + b0r  (fp16, K=16) =====
        float c[16][4];
        {
            const float* br = g_b0r + (size_t)(tile >> 1) * 128;
#pragma unroll
            for (int j = 0; j < 16; j++) {
                float2 bb = *reinterpret_cast<const float2*>(br + 8 * j + 2 * lane4);
                c[j][0] = bb.x; c[j][1] = bb.y;
                c[j][2] = bb.x; c[j][3] = bb.y;
            }
        }
        {
            uint32_t ah[4];
            LDSM4(ah, sb + FEAT_OFF + ((m0 + a_row) * FSTR + a_k8) * 2);
#pragma unroll
            for (int g = 0; g < 8; g++) {
                uint32_t bh[4];
                LDSM4(bh, sb + W0_OFF + ((16 * g + b_row) * FSTR + b_k8) * 2);
                MMA16816(c[2 * g],     ah, bh[0], bh[1]);
                MMA16816(c[2 * g + 1], ah, bh[2], bh[3]);
            }
        }

        // ===== epilogue1: relu -> fp16 A-fragments (in regs) =====
        uint32_t a2[8][4];
#pragma unroll
        for (int tk = 0; tk < 8; tk++) {
            a2[tk][0] = h2pack(fmaxf(c[2 * tk][0], 0.f),     fmaxf(c[2 * tk][1], 0.f));
            a2[tk][1] = h2pack(fmaxf(c[2 * tk][2], 0.f),     fmaxf(c[2 * tk][3], 0.f));
            a2[tk][2] = h2pack(fmaxf(c[2 * tk + 1][0], 0.f), fmaxf(c[2 * tk + 1][1], 0.f));
            a2[tk][3] = h2pack(fmaxf(c[2 * tk + 1][2], 0.f), fmaxf(c[2 * tk + 1][3], 0.f));
        }

        // ===== GEMM2: d = h1 @ w1^T + b1  (fp16, K=128) =====
        float d[16][4];
#pragma unroll
        for (int j = 0; j < 16; j++) {
            int col0 = 8 * j + 2 * lane4;
            d[j][0] = b1s[col0]; d[j][1] = b1s[col0 + 1];
            d[j][2] = d[j][0];   d[j][3] = d[j][1];
        }
#pragma unroll
        for (int tk = 0; tk < 8; tk++) {
#pragma unroll
            for (int g = 0; g < 8; g++) {
                uint32_t wh[4];
                LDSM4(wh, sb + W1_OFF + ((16 * g + b_row) * HSTR + tk * 16 + b_k8) * 2);
                MMA16816(d[2 * g],     a2[tk], wh[0], wh[1]);
                MMA16816(d[2 * g + 1], a2[tk], wh[2], wh[3]);
            }
        }

        // ===== epilogue2: rgb = sigmoid(relu(d) @ w2 + b2) =====
        {
            float p00 = 0.f, p01 = 0.f, p02 = 0.f;
            float p10 = 0.f, p11 = 0.f, p12 = 0.f;
#pragma unroll
            for (int j = 0; j < 16; j++) {
                int col0 = 8 * j + 2 * lane4;
                float h00 = fmaxf(d[j][0], 0.f), h01 = fmaxf(d[j][1], 0.f);
                float h10 = fmaxf(d[j][2], 0.f), h11 = fmaxf(d[j][3], 0.f);
                const float* wA = w2s + col0 * 3;
                const float* wB = w2s + (col0 + 1) * 3;
                p00 += h00 * wA[0] + h01 * wB[0];
                p01 += h00 * wA[1] + h01 * wB[1];
                p02 += h00 * wA[2] + h01 * wB[2];
                p10 += h10 * wA[0] + h11 * wB[0];
                p11 += h10 * wA[1] + h11 * wB[1];
                p12 += h10 * wA[2] + h11 * wB[2];
            }
#pragma unroll
            for (int sh = 1; sh <= 2; sh <<= 1) {
                p00 += __shfl_xor_sync(0xffffffffu, p00, sh);
                p01 += __shfl_xor_sync(0xffffffffu, p01, sh);
                p02 += __shfl_xor_sync(0xffffffffu, p02, sh);
                p10 += __shfl_xor_sync(0xffffffffu, p10, sh);
                p11 += __shfl_xor_sync(0xffffffffu, p11, sh);
                p12 += __shfl_xor_sync(0xffffffffu, p12, sh);
            }
            if (lane4 == 0) {
                int gs0 = tile * TILE + m0 + laneq;
                int gs1 = gs0 + 8;
                g_rgb[(size_t)gs0 * 3 + 0] = 1.0f / (1.0f + expf(-(p00 + b2s[0])));
                g_rgb[(size_t)gs0 * 3 + 1] = 1.0f / (1.0f + expf(-(p01 + b2s[1])));
                g_rgb[(size_t)gs0 * 3 + 2] = 1.0f / (1.0f + expf(-(p02 + b2s[2])));
                g_rgb[(size_t)gs1 * 3 + 0] = 1.0f / (1.0f + expf(-(p10 + b2s[0])));
                g_rgb[(size_t)gs1 * 3 + 1] = 1.0f / (1.0f + expf(-(p11 + b2s[1])));
                g_rgb[(size_t)gs1 * 3 + 2] = 1.0f / (1.0f + expf(-(p12 + b2s[2])));
            }
        }
        __syncthreads();
    }
}

// ---------------- kernel 3: per-ray composite ----------------
__global__ void k_compose(float* __restrict__ out) {
    __shared__ float s_scan[256];
    __shared__ float s_r[256], s_g[256], s_b[256];
    int ray = blockIdx.x;
    int t = threadIdx.x;
    int gs = ray * 256 + t;

    float q = 0.5f * g_sp[gs];
    s_scan[t] = q;
    __syncthreads();
#pragma unroll
    for (int off = 1; off < 256; off <<= 1) {
        float v = (t >= off) ? s_scan[t - off] : 0.0f;
        __syncthreads();
        s_scan[t] += v;
        __syncthreads();
    }
    float incl = s_scan[t];
    float T_excl = expf(-(incl - q));
    float alpha = 1.0f - expf(-q);
    float wgt = alpha * T_excl;

    s_r[t] = wgt * g_rgb[(size_t)gs * 3 + 0];
    s_g[t] = wgt * g_rgb[(size_t)gs * 3 + 1];
    s_b[t] = wgt * g_rgb[(size_t)gs * 3 + 2];
    __syncthreads();
    for (int off = 128; off > 0; off >>= 1) {
        if (t < off) {
            s_r[t] += s_r[t + off];
            s_g[t] += s_g[t + off];
            s_b[t] += s_b[t + off];
        }
        __syncthreads();
    }
    if (t == 0) {
        float ainv = expf(-s_scan[255]);
        out[ray * 3 + 0] = s_r[0] + ainv;
        out[ray * 3 + 1] = s_g[0] + ainv;
        out[ray * 3 + 2] = s_b[0] + ainv;
    }
}

// ---------------- launch ----------------
extern "C" void kernel_launch(void* const* d_in, const int* in_sizes, int n_in,
                              void* d_out, int out_size) {
    const float* pts      = (const float*)d_in[0];
    const float* viewdirs = (const float*)d_in[1];
    const float* dens     = (const float*)d_in[2];
    const float* k0       = (const float*)d_in[3];
    const float* w0g      = (const float*)d_in[4];
    const float* b0g      = (const float*)d_in[5];
    const float* w1g      = (const float*)d_in[6];
    const float* b1g      = (const float*)d_in[7];
    const float* w2g      = (const float*)d_in[8];
    const float* b2g      = (const float*)d_in[9];
    float* out = (float*)d_out;

    cudaFuncSetAttribute(k_mlp, cudaFuncAttributeMaxDynamicSharedMemorySize, SMEM_TOTAL);

    k_raybias<<<NRAYS, 128>>>(viewdirs, w0g, b0g);
    k_transpose<<<V / 256, 256>>>(dens, k0);
    k_mlp<<<304, 256, SMEM_TOTAL>>>(pts, w0g, w1g, b1g, w2g, b2g);
    k_compose<<<NRAYS, 256>>>(out);
}

// round 7
// speedup vs baseline: 6.3160x; 1.0824x over previous
#include <cuda_runtime.h>
#include <cuda_fp16.h>
#include <cstdint>
#include <math.h>

// ---------------- problem constants ----------------
#define G        160
#define V        (G*G*G)          // 4,096,000 voxels
#define NRAYS    4096
#define S        256
#define NS       (NRAYS*S)        // 1,048,576 samples
#define TILE     128
#define NTILES   (NS/TILE)        // 8192
#define ACT_SHIFT (-4.5951198501345898f)   // log(0.01/0.99)

#define FSTR     40               // fp16 elems/row, feat + w0 tiles (K=32 used + 8 pad)
#define HSTR     136              // fp16 elems/row, w1 tiles (K=128 + pad)

// ---------------- scratch ----------------
// packed voxel: bytes 0-23 = ch0..11 fp16, bytes 24-27 = density fp32, 28-31 pad
__device__ uint4 g_pack[(size_t)V * 2];
__device__ float g_sp[NS];                  // softplus(dens + shift)
__device__ float g_rgb[(size_t)NS * 3];     // per-sample rgb (post-sigmoid)
__device__ float g_b0r[(size_t)NRAYS * 128];// per-ray fused bias: b0 + emb@w0[12:39]

// ---------------- smem layout (byte offsets) ----------------
#define FEAT_OFF  0
#define W0_OFF    (FEAT_OFF + 128*FSTR*2)     // 10240
#define W1_OFF    (W0_OFF   + 128*FSTR*2)     // 20480
#define PSD_OFF   (W1_OFF   + 128*HSTR*2)     // 55296  (128 f32 density partials)
#define B0RS_OFF  (PSD_OFF  + 512)            // 55808  (128 f32 per-ray bias)
#define B1S_OFF   (B0RS_OFF + 512)            // 56320
#define W2P_OFF   (B1S_OFF  + 512)            // 56832  (half2[3][64] = 768B)
#define B2S_OFF   (W2P_OFF  + 768)            // 57600
#define SMEM_TOTAL (B2S_OFF + 64)

// ---------------- PTX helpers (baseline ISA only) ----------------
__device__ __forceinline__ uint32_t smem_u32(const void* p) {
    uint32_t a;
    asm("{ .reg .u64 tmp; cvta.to.shared.u64 tmp, %1; cvt.u32.u64 %0, tmp; }" : "=r"(a) : "l"(p));
    return a;
}
#define LDSM4(r, a) \
    asm volatile("ldmatrix.sync.aligned.m8n8.x4.shared.b16 {%0,%1,%2,%3}, [%4];" \
        : "=r"((r)[0]), "=r"((r)[1]), "=r"((r)[2]), "=r"((r)[3]) : "r"(a))

#define MMA16816(c, a, b0_, b1_) \
    asm volatile("mma.sync.aligned.m16n8k16.row.col.f32.f16.f16.f32 " \
        "{%0,%1,%2,%3}, {%4,%5,%6,%7}, {%8,%9}, {%0,%1,%2,%3};" \
        : "+f"((c)[0]), "+f"((c)[1]), "+f"((c)[2]), "+f"((c)[3]) \
        : "r"((a)[0]), "r"((a)[1]), "r"((a)[2]), "r"((a)[3]), "r"(b0_), "r"(b1_))

__device__ __forceinline__ uint32_t h2pack(float lo, float hi) {
    __half2 h = __floats2half2_rn(lo, hi);     // .x = lo (low 16 bits)
    return *reinterpret_cast<uint32_t*>(&h);
}
__device__ __forceinline__ __half2 u2h2(uint32_t w) {
    return *reinterpret_cast<__half2*>(&w);
}

// ---------------- kernel 0: per-ray fused bias ----------------
__global__ __launch_bounds__(128) void k_raybias(const float* __restrict__ vdirs,
                                                 const float* __restrict__ w0g,
                                                 const float* __restrict__ b0g) {
    __shared__ float emb[28];
    const int ray = blockIdx.x;
    const int t = threadIdx.x;
    float vx = __ldg(vdirs + ray * 3 + 0);
    float vy = __ldg(vdirs + ray * 3 + 1);
    float vz = __ldg(vdirs + ray * 3 + 2);
    float inv = rsqrtf(vx * vx + vy * vy + vz * vz);
    vx *= inv; vy *= inv; vz *= inv;
    if (t < 27) {
        if (t < 3) {
            emb[t] = (t == 0) ? vx : (t == 1) ? vy : vz;
        } else if (t < 15) {
            int i = t - 3, d = i >> 2, f = i & 3;
            float v = (d == 0) ? vx : (d == 1) ? vy : vz;
            emb[t] = sinf(v * (float)(1 << f));
        } else {
            int i = t - 15, d = i >> 2, f = i & 3;
            float v = (d == 0) ? vx : (d == 1) ? vy : vz;
            emb[t] = cosf(v * (float)(1 << f));
        }
    }
    __syncthreads();
    float s = b0g[t];
#pragma unroll
    for (int e = 0; e < 27; e++) s += emb[e] * w0g[(12 + e) * 128 + t];
    g_b0r[(size_t)ray * 128 + t] = s;
}

// ---------------- kernel 1: transpose + fp16-pack grids ----------
__global__ __launch_bounds__(256) void k_transpose(const float* __restrict__ dens,
                                                   const float* __restrict__ k0) {
    int v = blockIdx.x * 256 + threadIdx.x;
    uint32_t h[6];
#pragma unroll
    for (int j = 0; j < 6; j++) {
        float a = __ldg(k0 + (size_t)(2 * j) * V + v);
        float b = __ldg(k0 + (size_t)(2 * j + 1) * V + v);
        h[j] = h2pack(a, b);
    }
    float dd = __ldg(dens + v);
    uint4* out = g_pack + (size_t)v * 2;
    out[0] = make_uint4(h[0], h[1], h[2], h[3]);
    out[1] = make_uint4(h[4], h[5], __float_as_uint(dd), 0u);
}

// ---------------- kernel 2: persistent featurize + fp16 mma MLP ----------------
__global__ __launch_bounds__(256, 2)
void k_mlp(const float* __restrict__ pts,
           const float* __restrict__ w0g,
           const float* __restrict__ w1g, const float* __restrict__ b1g,
           const float* __restrict__ w2g, const float* __restrict__ b2g) {
    extern __shared__ char sm[];
    const uint32_t sb = smem_u32(sm);
    const int t = threadIdx.x;
    const int lane = t & 31;
    const int warp = t >> 5;

    float* psd  = reinterpret_cast<float*>(sm + PSD_OFF);
    float* b0rs = reinterpret_cast<float*>(sm + B0RS_OFF);
    float* b1s  = reinterpret_cast<float*>(sm + B1S_OFF);
    uint32_t* w2p = reinterpret_cast<uint32_t*>(sm + W2P_OFF);   // [3][64]
    float* b2s  = reinterpret_cast<float*>(sm + B2S_OFF);

    // ---- zero feat + w0 regions (pads stay zero) ----
    for (int i = t; i < W1_OFF / 4; i += 256)
        reinterpret_cast<uint32_t*>(sm)[i] = 0;
    __syncthreads();

    // ---- stage weights (once per block) ----
    // w0 rows 0..11: B0[n][k] = w0[k][n], duplicated at k+12 (corner-half split)
    for (int i = t; i < 12 * 128; i += 256) {
        int k = i >> 7, n = i & 127;
        __half v = __float2half_rn(w0g[i]);
        reinterpret_cast<__half*>(sm + W0_OFF)[n * FSTR + k] = v;
        reinterpret_cast<__half*>(sm + W0_OFF)[n * FSTR + 12 + k] = v;
    }
    for (int i = t; i < 128 * 128; i += 256) {
        int k = i >> 7, n = i & 127;
        reinterpret_cast<__half*>(sm + W1_OFF)[n * HSTR + k] = __float2half_rn(w1g[i]);
    }
    if (t < 128) b1s[t] = b1g[t];
    if (t < 192) {
        int c = t / 64, i = t % 64;
        w2p[c * 64 + i] = h2pack(w2g[(2 * i) * 3 + c], w2g[(2 * i + 1) * 3 + c]);
    }
    if (t < 3) b2s[t] = b2g[t];
    __syncthreads();

    // ---- ldmatrix lane addressing ----
    const int a_row = (((lane >> 3) & 1) << 3) + (lane & 7);
    const int a_k8  = (lane >> 4) << 3;
    const int b_row = ((lane >> 4) << 3) + (lane & 7);
    const int b_k8  = ((lane >> 3) & 1) << 3;

    const int m0 = warp << 4;
    const int lane4 = lane & 3;
    const int laneq = lane >> 2;

    const int s_id = t & 127;      // sample within tile
    const int half = t >> 7;       // corner-half for featurize

    for (int tile = blockIdx.x; tile < NTILES; tile += gridDim.x) {
        const int gs = tile * TILE + s_id;

        // ===== featurize: 2 threads/sample; partials land in separate K-cols =====
        {
            const float* pp = pts + (size_t)gs * 3;
            float f[3]; int i0[3];
#pragma unroll
            for (int d = 0; d < 3; d++) {
                float u = (pp[d] + 1.0f) * (0.5f * (G - 1));
                u = fminf(fmaxf(u, 0.0f), (float)(G - 1));
                int ii = (int)floorf(u);
                ii = min(ii, G - 2);
                f[d] = u - (float)ii;
                i0[d] = ii;
            }
            float wxh = half ? f[0] : (1.0f - f[0]);
            float wy[2] = {1.0f - f[1], f[1]};
            float wz[2] = {1.0f - f[2], f[2]};

            __half2 acc2[6];
#pragma unroll
            for (int j = 0; j < 6; j++) acc2[j] = __float2half2_rn(0.0f);
            float dacc = 0.0f;
            const int xbase = ((i0[0] + half) * G + i0[1]) * G + i0[2];
#pragma unroll
            for (int dy = 0; dy < 2; dy++)
#pragma unroll
            for (int dz = 0; dz < 2; dz++) {
                float wgt = wxh * wy[dy] * wz[dz];
                __half2 wh = __float2half2_rn(wgt);
                int vox = xbase + dy * G + dz;
                const uint4* cp = g_pack + (size_t)vox * 2;
                uint4 A = cp[0], B = cp[1];
                acc2[0] = __hfma2(wh, u2h2(A.x), acc2[0]);
                acc2[1] = __hfma2(wh, u2h2(A.y), acc2[1]);
                acc2[2] = __hfma2(wh, u2h2(A.z), acc2[2]);
                acc2[3] = __hfma2(wh, u2h2(A.w), acc2[3]);
                acc2[4] = __hfma2(wh, u2h2(B.x), acc2[4]);
                acc2[5] = __hfma2(wh, u2h2(B.y), acc2[5]);
                dacc += wgt * __uint_as_float(B.z);
            }
            uint32_t* frow = reinterpret_cast<uint32_t*>(sm + FEAT_OFF + (size_t)s_id * FSTR * 2);
#pragma unroll
            for (int j = 0; j < 6; j++)
                frow[half * 6 + j] = *reinterpret_cast<uint32_t*>(&acc2[j]);
            if (half) {
                psd[s_id] = dacc;
                b0rs[s_id] = g_b0r[(size_t)(tile >> 1) * 128 + s_id];
            }
            __syncthreads();
            if (!half) {
                float dd = dacc + psd[s_id] + ACT_SHIFT;
                g_sp[gs] = (dd > 15.0f) ? dd : log1pf(expf(dd));
            }
        }

        // ===== GEMM1: c = feat @ W0dup^T + b0r  (fp16, K=32) =====
        float c[16][4];
#pragma unroll
        for (int j = 0; j < 16; j++) {
            float2 bb = *reinterpret_cast<const float2*>(b0rs + 8 * j + 2 * lane4);
            c[j][0] = bb.x; c[j][1] = bb.y;
            c[j][2] = bb.x; c[j][3] = bb.y;
        }
        {
            uint32_t ah[2][4];
            LDSM4(ah[0], sb + FEAT_OFF + ((m0 + a_row) * FSTR + a_k8) * 2);
            LDSM4(ah[1], sb + FEAT_OFF + ((m0 + a_row) * FSTR + 16 + a_k8) * 2);
#pragma unroll
            for (int tk = 0; tk < 2; tk++) {
#pragma unroll
                for (int g = 0; g < 8; g++) {
                    uint32_t bh[4];
                    LDSM4(bh, sb + W0_OFF + ((16 * g + b_row) * FSTR + tk * 16 + b_k8) * 2);
                    MMA16816(c[2 * g],     ah[tk], bh[0], bh[1]);
                    MMA16816(c[2 * g + 1], ah[tk], bh[2], bh[3]);
                }
            }
        }

        // ===== epilogue1: relu -> fp16 A-fragments (in regs) =====
        uint32_t a2[8][4];
#pragma unroll
        for (int tk = 0; tk < 8; tk++) {
            a2[tk][0] = h2pack(fmaxf(c[2 * tk][0], 0.f),     fmaxf(c[2 * tk][1], 0.f));
            a2[tk][1] = h2pack(fmaxf(c[2 * tk][2], 0.f),     fmaxf(c[2 * tk][3], 0.f));
            a2[tk][2] = h2pack(fmaxf(c[2 * tk + 1][0], 0.f), fmaxf(c[2 * tk + 1][1], 0.f));
            a2[tk][3] = h2pack(fmaxf(c[2 * tk + 1][2], 0.f), fmaxf(c[2 * tk + 1][3], 0.f));
        }

        // ===== GEMM2: d = h1 @ w1^T + b1  (fp16, K=128) =====
        float d[16][4];
#pragma unroll
        for (int j = 0; j < 16; j++) {
            int col0 = 8 * j + 2 * lane4;
            d[j][0] = b1s[col0]; d[j][1] = b1s[col0 + 1];
            d[j][2] = d[j][0];   d[j][3] = d[j][1];
        }
#pragma unroll
        for (int tk = 0; tk < 8; tk++) {
#pragma unroll
            for (int g = 0; g < 8; g++) {
                uint32_t wh[4];
                LDSM4(wh, sb + W1_OFF + ((16 * g + b_row) * HSTR + tk * 16 + b_k8) * 2);
                MMA16816(d[2 * g],     a2[tk], wh[0], wh[1]);
                MMA16816(d[2 * g + 1], a2[tk], wh[2], wh[3]);
            }
        }

        // ===== epilogue2: rgb = sigmoid(relu(d) @ w2 + b2), HFMA2 packed =====
        {
            __half2 qA0 = __float2half2_rn(0.f), qA1 = qA0, qA2 = qA0;
            __half2 qB0 = qA0, qB1 = qA0, qB2 = qA0;
#pragma unroll
            for (int j = 0; j < 16; j++) {
                int idx = 4 * j + lane4;
                __half2 hA = __floats2half2_rn(fmaxf(d[j][0], 0.f), fmaxf(d[j][1], 0.f));
                __half2 hB = __floats2half2_rn(fmaxf(d[j][2], 0.f), fmaxf(d[j][3], 0.f));
                __half2 w0h = u2h2(w2p[idx]);
                __half2 w1h = u2h2(w2p[64 + idx]);
                __half2 w2h = u2h2(w2p[128 + idx]);
                qA0 = __hfma2(hA, w0h, qA0);
                qA1 = __hfma2(hA, w1h, qA1);
                qA2 = __hfma2(hA, w2h, qA2);
                qB0 = __hfma2(hB, w0h, qB0);
                qB1 = __hfma2(hB, w1h, qB1);
                qB2 = __hfma2(hB, w2h, qB2);
            }
            float p00 = __low2float(qA0) + __high2float(qA0);
            float p01 = __low2float(qA1) + __high2float(qA1);
            float p02 = __low2float(qA2) + __high2float(qA2);
            float p10 = __low2float(qB0) + __high2float(qB0);
            float p11 = __low2float(qB1) + __high2float(qB1);
            float p12 = __low2float(qB2) + __high2float(qB2);
#pragma unroll
            for (int sh = 1; sh <= 2; sh <<= 1) {
                p00 += __shfl_xor_sync(0xffffffffu, p00, sh);
                p01 += __shfl_xor_sync(0xffffffffu, p01, sh);
                p02 += __shfl_xor_sync(0xffffffffu, p02, sh);
                p10 += __shfl_xor_sync(0xffffffffu, p10, sh);
                p11 += __shfl_xor_sync(0xffffffffu, p11, sh);
                p12 += __shfl_xor_sync(0xffffffffu, p12, sh);
            }
            if (lane4 == 0) {
                int gs0 = tile * TILE + m0 + laneq;
                int gs1 = gs0 + 8;
                g_rgb[(size_t)gs0 * 3 + 0] = 1.0f / (1.0f + expf(-(p00 + b2s[0])));
                g_rgb[(size_t)gs0 * 3 + 1] = 1.0f / (1.0f + expf(-(p01 + b2s[1])));
                g_rgb[(size_t)gs0 * 3 + 2] = 1.0f / (1.0f + expf(-(p02 + b2s[2])));
                g_rgb[(size_t)gs1 * 3 + 0] = 1.0f / (1.0f + expf(-(p10 + b2s[0])));
                g_rgb[(size_t)gs1 * 3 + 1] = 1.0f / (1.0f + expf(-(p11 + b2s[1])));
                g_rgb[(size_t)gs1 * 3 + 2] = 1.0f / (1.0f + expf(-(p12 + b2s[2])));
            }
        }
        __syncthreads();
    }
}

// ---------------- kernel 3: per-ray composite ----------------
__global__ void k_compose(float* __restrict__ out) {
    __shared__ float s_scan[256];
    __shared__ float s_r[256], s_g[256], s_b[256];
    int ray = blockIdx.x;
    int t = threadIdx.x;
    int gs = ray * 256 + t;

    float q = 0.5f * g_sp[gs];
    s_scan[t] = q;
    __syncthreads();
#pragma unroll
    for (int off = 1; off < 256; off <<= 1) {
        float v = (t >= off) ? s_scan[t - off] : 0.0f;
        __syncthreads();
        s_scan[t] += v;
        __syncthreads();
    }
    float incl = s_scan[t];
    float T_excl = expf(-(incl - q));
    float alpha = 1.0f - expf(-q);
    float wgt = alpha * T_excl;

    s_r[t] = wgt * g_rgb[(size_t)gs * 3 + 0];
    s_g[t] = wgt * g_rgb[(size_t)gs * 3 + 1];
    s_b[t] = wgt * g_rgb[(size_t)gs * 3 + 2];
    __syncthreads();
    for (int off = 128; off > 0; off >>= 1) {
        if (t < off) {
            s_r[t] += s_r[t + off];
            s_g[t] += s_g[t + off];
            s_b[t] += s_b[t + off];
        }
        __syncthreads();
    }
    if (t == 0) {
        float ainv = expf(-s_scan[255]);
        out[ray * 3 + 0] = s_r[0] + ainv;
        out[ray * 3 + 1] = s_g[0] + ainv;
        out[ray * 3 + 2] = s_b[0] + ainv;
    }
}

// ---------------- launch ----------------
extern "C" void kernel_launch(void* const* d_in, const int* in_sizes, int n_in,
                              void* d_out, int out_size) {
    const float* pts      = (const float*)d_in[0];
    const float* viewdirs = (const float*)d_in[1];
    const float* dens     = (const float*)d_in[2];
    const float* k0       = (const float*)d_in[3];
    const float* w0g      = (const float*)d_in[4];
    const float* b0g      = (const float*)d_in[5];
    const float* w1g      = (const float*)d_in[6];
    const float* b1g      = (const float*)d_in[7];
    const float* w2g      = (const float*)d_in[8];
    const float* b2g      = (const float*)d_in[9];
    float* out = (float*)d_out;

    cudaFuncSetAttribute(k_mlp, cudaFuncAttributeMaxDynamicSharedMemorySize, SMEM_TOTAL);

    k_raybias<<<NRAYS, 128>>>(viewdirs, w0g, b0g);
    k_transpose<<<V / 256, 256>>>(dens, k0);
    k_mlp<<<304, 256, SMEM_TOTAL>>>(pts, w0g, w1g, b1g, w2g, b2g);
    k_compose<<<NRAYS, 256>>>(out);
}

// round 8
// speedup vs baseline: 6.4671x; 1.0239x over previous
#include <cuda_runtime.h>
#include <cuda_fp16.h>
#include <cstdint>
#include <math.h>

// ---------------- problem constants ----------------
#define G        160
#define V        (G*G*G)          // 4,096,000 voxels
#define NRAYS    4096
#define S        256
#define NS       (NRAYS*S)        // 1,048,576 samples
#define ACT_SHIFT (-4.5951198501345898f)   // log(0.01/0.99)

#define FSTR     24               // fp16 elems/row, feat + w0 tiles (K=16 incl pad)
#define HSTR     136              // fp16 elems/row, w1 tiles (K=128 + pad)
#define GRID_MLP 304

// ---------------- scratch ----------------
// packed voxel: bytes 0-23 = ch0..11 fp16, bytes 24-27 = density fp32, 28-31 pad
__device__ uint4 g_pack[(size_t)V * 2];
__device__ float g_b0r[(size_t)NRAYS * 128];// per-ray fused bias: b0 + emb@w0[12:39]

// ---------------- smem layout (byte offsets) ----------------
#define FEAT_OFF  0                            // 256 x FSTR fp16 = 12288
#define W0_OFF    (FEAT_OFF + 256*FSTR*2)      // 12288 (+6144)
#define W1_OFF    (W0_OFF   + 128*FSTR*2)      // 18432 (+34816)
#define SPQ_OFF   (W1_OFF   + 128*HSTR*2)      // 53248 (256 f32 = 1024)
#define RGBR_OFF  (SPQ_OFF  + 1024)            // 54272
#define RGBG_OFF  (RGBR_OFF + 1024)            // 55296
#define RGBB_OFF  (RGBG_OFF + 1024)            // 56320
#define WTOT_OFF  (RGBB_OFF + 1024)            // 57344 (8 f32 warp totals + total)
#define WPART_OFF (WTOT_OFF + 64)              // 57408 (8 x 3 f32 partials)
#define B0RS_OFF  (WPART_OFF + 128)            // 57536 (128 f32)
#define B1S_OFF   (B0RS_OFF + 512)             // 58048
#define W2P_OFF   (B1S_OFF  + 512)             // 58560 (half2[3][64] = 768B)
#define B2S_OFF   (W2P_OFF  + 768)             // 59328
#define SMEM_TOTAL (B2S_OFF + 64)              // ~59.4 KB -> 2 CTAs/SM

// ---------------- PTX helpers (baseline ISA only) ----------------
__device__ __forceinline__ uint32_t smem_u32(const void* p) {
    uint32_t a;
    asm("{ .reg .u64 tmp; cvta.to.shared.u64 tmp, %1; cvt.u32.u64 %0, tmp; }" : "=r"(a) : "l"(p));
    return a;
}
#define LDSM4(r, a) \
    asm volatile("ldmatrix.sync.aligned.m8n8.x4.shared.b16 {%0,%1,%2,%3}, [%4];" \
        : "=r"((r)[0]), "=r"((r)[1]), "=r"((r)[2]), "=r"((r)[3]) : "r"(a))

#define MMA16816(c, a, b0_, b1_) \
    asm volatile("mma.sync.aligned.m16n8k16.row.col.f32.f16.f16.f32 " \
        "{%0,%1,%2,%3}, {%4,%5,%6,%7}, {%8,%9}, {%0,%1,%2,%3};" \
        : "+f"((c)[0]), "+f"((c)[1]), "+f"((c)[2]), "+f"((c)[3]) \
        : "r"((a)[0]), "r"((a)[1]), "r"((a)[2]), "r"((a)[3]), "r"(b0_), "r"(b1_))

__device__ __forceinline__ uint32_t h2pack(float lo, float hi) {
    __half2 h = __floats2half2_rn(lo, hi);     // .x = lo (low 16 bits)
    return *reinterpret_cast<uint32_t*>(&h);
}
__device__ __forceinline__ __half2 u2h2(uint32_t w) {
    return *reinterpret_cast<__half2*>(&w);
}

// ---------------- kernel 0: per-ray fused bias ----------------
__global__ __launch_bounds__(128) void k_raybias(const float* __restrict__ vdirs,
                                                 const float* __restrict__ w0g,
                                                 const float* __restrict__ b0g) {
    __shared__ float emb[28];
    const int ray = blockIdx.x;
    const int t = threadIdx.x;
    float vx = __ldg(vdirs + ray * 3 + 0);
    float vy = __ldg(vdirs + ray * 3 + 1);
    float vz = __ldg(vdirs + ray * 3 + 2);
    float inv = rsqrtf(vx * vx + vy * vy + vz * vz);
    vx *= inv; vy *= inv; vz *= inv;
    if (t < 27) {
        if (t < 3) {
            emb[t] = (t == 0) ? vx : (t == 1) ? vy : vz;
        } else if (t < 15) {
            int i = t - 3, d = i >> 2, f = i & 3;
            float v = (d == 0) ? vx : (d == 1) ? vy : vz;
            emb[t] = sinf(v * (float)(1 << f));
        } else {
            int i = t - 15, d = i >> 2, f = i & 3;
            float v = (d == 0) ? vx : (d == 1) ? vy : vz;
            emb[t] = cosf(v * (float)(1 << f));
        }
    }
    __syncthreads();
    float s = b0g[t];
#pragma unroll
    for (int e = 0; e < 27; e++) s += emb[e] * w0g[(12 + e) * 128 + t];
    g_b0r[(size_t)ray * 128 + t] = s;
}

// ---------------- kernel 1: transpose + fp16-pack grids ----------
__global__ __launch_bounds__(256) void k_transpose(const float* __restrict__ dens,
                                                   const float* __restrict__ k0) {
    int v = blockIdx.x * 256 + threadIdx.x;
    uint32_t h[6];
#pragma unroll
    for (int j = 0; j < 6; j++) {
        float a = __ldg(k0 + (size_t)(2 * j) * V + v);
        float b = __ldg(k0 + (size_t)(2 * j + 1) * V + v);
        h[j] = h2pack(a, b);
    }
    float dd = __ldg(dens + v);
    uint4* out = g_pack + (size_t)v * 2;
    out[0] = make_uint4(h[0], h[1], h[2], h[3]);
    out[1] = make_uint4(h[4], h[5], __float_as_uint(dd), 0u);
}

// ---------------- kernel 2: persistent ray-fused featurize + MLP + composite --
__global__ __launch_bounds__(256, 2)
void k_mlp(const float* __restrict__ pts,
           const float* __restrict__ w0g,
           const float* __restrict__ w1g, const float* __restrict__ b1g,
           const float* __restrict__ w2g, const float* __restrict__ b2g,
           float* __restrict__ out) {
    extern __shared__ char sm[];
    const uint32_t sb = smem_u32(sm);
    const int t = threadIdx.x;
    const int lane = t & 31;
    const int warp = t >> 5;

    float* spq  = reinterpret_cast<float*>(sm + SPQ_OFF);
    float* s_r  = reinterpret_cast<float*>(sm + RGBR_OFF);
    float* s_g  = reinterpret_cast<float*>(sm + RGBG_OFF);
    float* s_b  = reinterpret_cast<float*>(sm + RGBB_OFF);
    float* wtot = reinterpret_cast<float*>(sm + WTOT_OFF);
    float* wpart= reinterpret_cast<float*>(sm + WPART_OFF);
    float* b0rs = reinterpret_cast<float*>(sm + B0RS_OFF);
    float* b1s  = reinterpret_cast<float*>(sm + B1S_OFF);
    uint32_t* w2p = reinterpret_cast<uint32_t*>(sm + W2P_OFF);   // [3][64]
    float* b2s  = reinterpret_cast<float*>(sm + B2S_OFF);

    // ---- zero feat + w0 regions (K pads stay zero) ----
    for (int i = t; i < W1_OFF / 4; i += 256)
        reinterpret_cast<uint32_t*>(sm)[i] = 0;
    __syncthreads();

    // ---- stage weights (once per block) ----
    for (int i = t; i < 12 * 128; i += 256) {
        int k = i >> 7, n = i & 127;
        reinterpret_cast<__half*>(sm + W0_OFF)[n * FSTR + k] = __float2half_rn(w0g[i]);
    }
    for (int i = t; i < 128 * 128; i += 256) {
        int k = i >> 7, n = i & 127;
        reinterpret_cast<__half*>(sm + W1_OFF)[n * HSTR + k] = __float2half_rn(w1g[i]);
    }
    if (t < 128) b1s[t] = b1g[t];
    if (t < 192) {
        int c = t / 64, i = t % 64;
        w2p[c * 64 + i] = h2pack(w2g[(2 * i) * 3 + c], w2g[(2 * i + 1) * 3 + c]);
    }
    if (t < 3) b2s[t] = b2g[t];
    __syncthreads();

    // ---- ldmatrix lane addressing ----
    const int a_row = (((lane >> 3) & 1) << 3) + (lane & 7);
    const int a_k8  = (lane >> 4) << 3;
    const int b_row = ((lane >> 4) << 3) + (lane & 7);
    const int b_k8  = ((lane >> 3) & 1) << 3;

    const int m0 = warp << 4;
    const int lane4 = lane & 3;
    const int laneq = lane >> 2;

    for (int ray = blockIdx.x; ray < NRAYS; ray += GRID_MLP) {
        const int gs = ray * 256 + t;

        // ===== featurize: 1 thread per sample, 8 corners =====
        {
            const float* pp = pts + (size_t)gs * 3;
            float f[3]; int i0[3];
#pragma unroll
            for (int d = 0; d < 3; d++) {
                float u = (pp[d] + 1.0f) * (0.5f * (G - 1));
                u = fminf(fmaxf(u, 0.0f), (float)(G - 1));
                int ii = (int)floorf(u);
                ii = min(ii, G - 2);
                f[d] = u - (float)ii;
                i0[d] = ii;
            }
            float wx[2] = {1.0f - f[0], f[0]};
            float wy[2] = {1.0f - f[1], f[1]};
            float wz[2] = {1.0f - f[2], f[2]};

            __half2 acc2[6];
#pragma unroll
            for (int j = 0; j < 6; j++) acc2[j] = __float2half2_rn(0.0f);
            float dacc = 0.0f;
            const int base = (i0[0] * G + i0[1]) * G + i0[2];
#pragma unroll
            for (int dx = 0; dx < 2; dx++)
#pragma unroll
            for (int dy = 0; dy < 2; dy++)
#pragma unroll
            for (int dz = 0; dz < 2; dz++) {
                float wgt = wx[dx] * wy[dy] * wz[dz];
                __half2 wh = __float2half2_rn(wgt);
                int vox = base + (dx * G + dy) * G + dz;
                const uint4* cp = g_pack + (size_t)vox * 2;
                uint4 A = cp[0], B = cp[1];
                acc2[0] = __hfma2(wh, u2h2(A.x), acc2[0]);
                acc2[1] = __hfma2(wh, u2h2(A.y), acc2[1]);
                acc2[2] = __hfma2(wh, u2h2(A.z), acc2[2]);
                acc2[3] = __hfma2(wh, u2h2(A.w), acc2[3]);
                acc2[4] = __hfma2(wh, u2h2(B.x), acc2[4]);
                acc2[5] = __hfma2(wh, u2h2(B.y), acc2[5]);
                dacc += wgt * __uint_as_float(B.z);
            }
            uint32_t* frow = reinterpret_cast<uint32_t*>(sm + FEAT_OFF + (size_t)t * FSTR * 2);
#pragma unroll
            for (int j = 0; j < 6; j++)
                frow[j] = *reinterpret_cast<uint32_t*>(&acc2[j]);
            float dd = dacc + ACT_SHIFT;
            float sp = (dd > 15.0f) ? dd : log1pf(expf(dd));
            spq[t] = 0.5f * sp;                   // q = INTERVAL * softplus
            if (t < 128) b0rs[t] = g_b0r[(size_t)ray * 128 + t];
        }
        __syncthreads();

        // ===== two MMA passes: rows p*128 .. p*128+127 =====
#pragma unroll
        for (int p = 0; p < 2; p++) {
            const int rb = p << 7;

            // GEMM1: c = feat @ w0^T + b0r (fp16, K=16)
            float c[16][4];
#pragma unroll
            for (int j = 0; j < 16; j++) {
                float2 bb = *reinterpret_cast<const float2*>(b0rs + 8 * j + 2 * lane4);
                c[j][0] = bb.x; c[j][1] = bb.y;
                c[j][2] = bb.x; c[j][3] = bb.y;
            }
            {
                uint32_t ah[4];
                LDSM4(ah, sb + FEAT_OFF + ((rb + m0 + a_row) * FSTR + a_k8) * 2);
#pragma unroll
                for (int g = 0; g < 8; g++) {
                    uint32_t bh[4];
                    LDSM4(bh, sb + W0_OFF + ((16 * g + b_row) * FSTR + b_k8) * 2);
                    MMA16816(c[2 * g],     ah, bh[0], bh[1]);
                    MMA16816(c[2 * g + 1], ah, bh[2], bh[3]);
                }
            }

            // epilogue1: relu -> fp16 A-fragments
            uint32_t a2[8][4];
#pragma unroll
            for (int tk = 0; tk < 8; tk++) {
                a2[tk][0] = h2pack(fmaxf(c[2 * tk][0], 0.f),     fmaxf(c[2 * tk][1], 0.f));
                a2[tk][1] = h2pack(fmaxf(c[2 * tk][2], 0.f),     fmaxf(c[2 * tk][3], 0.f));
                a2[tk][2] = h2pack(fmaxf(c[2 * tk + 1][0], 0.f), fmaxf(c[2 * tk + 1][1], 0.f));
                a2[tk][3] = h2pack(fmaxf(c[2 * tk + 1][2], 0.f), fmaxf(c[2 * tk + 1][3], 0.f));
            }

            // GEMM2: d = h1 @ w1^T + b1 (fp16, K=128)
            float d[16][4];
#pragma unroll
            for (int j = 0; j < 16; j++) {
                int col0 = 8 * j + 2 * lane4;
                d[j][0] = b1s[col0]; d[j][1] = b1s[col0 + 1];
                d[j][2] = d[j][0];   d[j][3] = d[j][1];
            }
#pragma unroll
            for (int tk = 0; tk < 8; tk++) {
#pragma unroll
                for (int g = 0; g < 8; g++) {
                    uint32_t wh[4];
                    LDSM4(wh, sb + W1_OFF + ((16 * g + b_row) * HSTR + tk * 16 + b_k8) * 2);
                    MMA16816(d[2 * g],     a2[tk], wh[0], wh[1]);
                    MMA16816(d[2 * g + 1], a2[tk], wh[2], wh[3]);
                }
            }

            // epilogue2: rgb = sigmoid(relu(d) @ w2 + b2) -> smem rgb buffers
            {
                __half2 qA0 = __float2half2_rn(0.f), qA1 = qA0, qA2 = qA0;
                __half2 qB0 = qA0, qB1 = qA0, qB2 = qA0;
#pragma unroll
                for (int j = 0; j < 16; j++) {
                    int idx = 4 * j + lane4;
                    __half2 hA = __floats2half2_rn(fmaxf(d[j][0], 0.f), fmaxf(d[j][1], 0.f));
                    __half2 hB = __floats2half2_rn(fmaxf(d[j][2], 0.f), fmaxf(d[j][3], 0.f));
                    __half2 w0h = u2h2(w2p[idx]);
                    __half2 w1h = u2h2(w2p[64 + idx]);
                    __half2 w2h = u2h2(w2p[128 + idx]);
                    qA0 = __hfma2(hA, w0h, qA0);
                    qA1 = __hfma2(hA, w1h, qA1);
                    qA2 = __hfma2(hA, w2h, qA2);
                    qB0 = __hfma2(hB, w0h, qB0);
                    qB1 = __hfma2(hB, w1h, qB1);
                    qB2 = __hfma2(hB, w2h, qB2);
                }
                float p00 = __low2float(qA0) + __high2float(qA0);
                float p01 = __low2float(qA1) + __high2float(qA1);
                float p02 = __low2float(qA2) + __high2float(qA2);
                float p10 = __low2float(qB0) + __high2float(qB0);
                float p11 = __low2float(qB1) + __high2float(qB1);
                float p12 = __low2float(qB2) + __high2float(qB2);
#pragma unroll
                for (int sh = 1; sh <= 2; sh <<= 1) {
                    p00 += __shfl_xor_sync(0xffffffffu, p00, sh);
                    p01 += __shfl_xor_sync(0xffffffffu, p01, sh);
                    p02 += __shfl_xor_sync(0xffffffffu, p02, sh);
                    p10 += __shfl_xor_sync(0xffffffffu, p10, sh);
                    p11 += __shfl_xor_sync(0xffffffffu, p11, sh);
                    p12 += __shfl_xor_sync(0xffffffffu, p12, sh);
                }
                if (lane4 == 0) {
                    int r0 = rb + m0 + laneq;
                    int r1 = r0 + 8;
                    s_r[r0] = 1.0f / (1.0f + expf(-(p00 + b2s[0])));
                    s_g[r0] = 1.0f / (1.0f + expf(-(p01 + b2s[1])));
                    s_b[r0] = 1.0f / (1.0f + expf(-(p02 + b2s[2])));
                    s_r[r1] = 1.0f / (1.0f + expf(-(p10 + b2s[0])));
                    s_g[r1] = 1.0f / (1.0f + expf(-(p11 + b2s[1])));
                    s_b[r1] = 1.0f / (1.0f + expf(-(p12 + b2s[2])));
                }
            }
        }
        __syncthreads();

        // ===== composite (in-block): warp-shuffle scan of q, weight, reduce ====
        {
            float q = spq[t];
            float v = q;
#pragma unroll
            for (int off = 1; off < 32; off <<= 1) {
                float u = __shfl_up_sync(0xffffffffu, v, off);
                if (lane >= off) v += u;
            }
            if (lane == 31) wtot[warp] = v;
            __syncthreads();
            if (t < 8) {
                float w = wtot[t];
                float e = 0.0f;
#pragma unroll
                for (int off = 1; off < 8; off <<= 1) {
                    float u = __shfl_up_sync(0xffu, w, off);
                    if (t >= off) w += u;
                }
                e = w - wtot[t];           // exclusive via incl - own? no: need excl of warp sums
                wtot[t] = w;               // inclusive warp-total scan
                if (t == 7) wtot[8] = w;   // grand total
            }
            __syncthreads();
            float incl = v + ((warp > 0) ? wtot[warp - 1] : 0.0f);
            float T_excl = expf(-(incl - q));
            float alpha = 1.0f - expf(-q);
            float wgt = alpha * T_excl;

            float rr = wgt * s_r[t];
            float gg = wgt * s_g[t];
            float bb = wgt * s_b[t];
#pragma unroll
            for (int sh = 16; sh > 0; sh >>= 1) {
                rr += __shfl_xor_sync(0xffffffffu, rr, sh);
                gg += __shfl_xor_sync(0xffffffffu, gg, sh);
                bb += __shfl_xor_sync(0xffffffffu, bb, sh);
            }
            if (lane == 0) {
                wpart[warp * 3 + 0] = rr;
                wpart[warp * 3 + 1] = gg;
                wpart[warp * 3 + 2] = bb;
            }
            __syncthreads();
            if (t == 0) {
                float ainv = expf(-wtot[8]);
                float o0 = ainv, o1 = ainv, o2 = ainv;
#pragma unroll
                for (int w8 = 0; w8 < 8; w8++) {
                    o0 += wpart[w8 * 3 + 0];
                    o1 += wpart[w8 * 3 + 1];
                    o2 += wpart[w8 * 3 + 2];
                }
                out[ray * 3 + 0] = o0;
                out[ray * 3 + 1] = o1;
                out[ray * 3 + 2] = o2;
            }
        }
        __syncthreads();
    }
}

// ---------------- launch ----------------
extern "C" void kernel_launch(void* const* d_in, const int* in_sizes, int n_in,
                              void* d_out, int out_size) {
    const float* pts      = (const float*)d_in[0];
    const float* viewdirs = (const float*)d_in[1];
    const float* dens     = (const float*)d_in[2];
    const float* k0       = (const float*)d_in[3];
    const float* w0g      = (const float*)d_in[4];
    const float* b0g      = (const float*)d_in[5];
    const float* w1g      = (const float*)d_in[6];
    const float* b1g      = (const float*)d_in[7];
    const float* w2g      = (const float*)d_in[8];
    const float* b2g      = (const float*)d_in[9];
    float* out = (float*)d_out;

    cudaFuncSetAttribute(k_mlp, cudaFuncAttributeMaxDynamicSharedMemorySize, SMEM_TOTAL);

    k_raybias<<<NRAYS, 128>>>(viewdirs, w0g, b0g);
    k_transpose<<<V / 256, 256>>>(dens, k0);
    k_mlp<<<GRID_MLP, 256, SMEM_TOTAL>>>(pts, w0g, w1g, b1g, w2g, b2g, out);
}